// round 12
// baseline (speedup 1.0000x reference)
#include <cuda_runtime.h>
#include <cuda_bf16.h>
#include <math.h>
#include <stdint.h>

// Problem constants
#define NB   16
#define NSEQ 1024
#define CK   512          // C*K

// -------- scratch (device globals; no allocation allowed) --------
__device__ float g_bufA[NB*NSEQ*CK];
__device__ float g_bufB[NB*NSEQ*CK];
__device__ float g_kA[NB*NSEQ*CK];
__device__ float g_kB[NB*NSEQ*CK];
__device__ float g_dq[NB*512*CK];     // shallow: detail-q; deep: per-b scratch (stride 262144)
__device__ float g_dk[NB*512*CK];     // shallow: detail-k; deep: per-b scratch
__device__ float g_Us[NB*1023*CK];
__device__ float g_Ud[NB*1023*CK];
__device__ float g_S[NB*4*2*16*CK];   // spectra: (b, tensor{dq,dk,qn,kn}, re/im, mode, ck)
__device__ float g_O[NB*2*2*16*CK];   // post-attn spectra: (b, which{s,d}, re/im, mode, ck)
__device__ __nv_bfloat16 g_Wthi[CK*CK];
__device__ __nv_bfloat16 g_Wtlo[CK*CK];
__device__ __nv_bfloat16 g_W2hi[CK*CK];
__device__ __nv_bfloat16 g_W2lo[CK*CK];
__device__ __nv_bfloat16 g_W3hi[CK*CK];
__device__ __nv_bfloat16 g_W3lo[CK*CK];

__device__ __forceinline__ uint32_t smem_u32(const void* p){
    uint32_t a;
    asm("{ .reg .u64 t; cvta.to.shared.u64 t, %1; cvt.u32.u64 %0, t; }" : "=r"(a) : "l"(p));
    return a;
}
__device__ __forceinline__ size_t doffs(int lev){
    return (size_t)16*512*(1024 - (1024 >> lev));
}

// ---- convW3: three W fp32 [K,N] -> transposed bf16 hi/lo pairs (one launch) ----
__global__ __launch_bounds__(256) void convW3_kernel(
    const float* __restrict__ W0, const float* __restrict__ W1, const float* __restrict__ W2,
    __nv_bfloat16* h0, __nv_bfloat16* l0,
    __nv_bfloat16* h1, __nv_bfloat16* l1,
    __nv_bfloat16* h2, __nv_bfloat16* l2)
{
    __shared__ float t[32][33];
    int z = blockIdx.z;
    const float* W = (z==0) ? W0 : (z==1) ? W1 : W2;
    __nv_bfloat16* hi = (z==0) ? h0 : (z==1) ? h1 : h2;
    __nv_bfloat16* lo = (z==0) ? l0 : (z==1) ? l1 : l2;
    int bx = blockIdx.x, by = blockIdx.y;
    int tx = threadIdx.x & 31, ty = threadIdx.x >> 5;
    for (int i = ty; i < 32; i += 8)
        t[i][tx] = W[(size_t)(bx*32 + i)*512 + by*32 + tx];
    __syncthreads();
    for (int i = ty; i < 32; i += 8){
        float v = t[tx][i];
        __nv_bfloat16 h = __float2bfloat16(v);
        size_t o = (size_t)(by*32 + i)*512 + bx*32 + tx;
        hi[o] = h;
        lo[o] = __float2bfloat16(v - __bfloat162float(h));
    }
}

__global__ void zero2_kernel(float* p1, float* p2, int n){
    int i = blockIdx.x*blockDim.x + threadIdx.x;
    if (i < n){ p1[i] = 0.f; p2[i] = 0.f; }
}

// ================= tensor-core GEMM (unchanged from R11) =================
#define STAGE_BYTES 40960
#define ARR_BYTES   10240
#define GEMM_SMEM   (2*STAGE_BYTES)

__device__ __forceinline__ void mma16816(float* d, const uint32_t* a, uint32_t b0, uint32_t b1){
    asm volatile(
        "mma.sync.aligned.m16n8k16.row.col.f32.bf16.bf16.f32 "
        "{%0,%1,%2,%3}, {%4,%5,%6,%7}, {%8,%9}, {%0,%1,%2,%3};"
        : "+f"(d[0]), "+f"(d[1]), "+f"(d[2]), "+f"(d[3])
        : "r"(a[0]), "r"(a[1]), "r"(a[2]), "r"(a[3]), "r"(b0), "r"(b1));
}
__device__ __forceinline__ void ldsm4(uint32_t* r, uint32_t addr){
    asm volatile("ldmatrix.sync.aligned.m8n8.x4.shared.b16 {%0,%1,%2,%3}, [%4];"
        : "=r"(r[0]), "=r"(r[1]), "=r"(r[2]), "=r"(r[3]) : "r"(addr));
}
__device__ __forceinline__ void loadB_async(
    const __nv_bfloat16* __restrict__ Bhi, const __nv_bfloat16* __restrict__ Blo,
    int n0, int k0, uint32_t sstage, int tid)
{
    #pragma unroll
    for (int t = 4; t < 8; t++){
        const int arr = t >> 1;
        const int row = (t & 1)*64 + (tid >> 2);
        const int seg = tid & 3;
        const __nv_bfloat16* g = ((arr == 2) ? Bhi : Blo) + (size_t)(n0 + row)*512 + k0 + seg*8;
        uint32_t d = sstage + arr*ARR_BYTES + row*80 + seg*16;
        asm volatile("cp.async.cg.shared.global [%0], [%1], 16;" :: "r"(d), "l"(g));
    }
}
__device__ __forceinline__ void prefetchA(const float* __restrict__ A,
    int m0, int k0, int tid, float4* pa)
{
    #pragma unroll
    for (int t = 0; t < 2; t++){
        int idx = tid + t*256;
        int row = idx >> 2, seg = idx & 3;
        const float* g = A + (size_t)(m0 + row)*512 + k0 + seg*8;
        pa[2*t]   = *(const float4*)g;
        pa[2*t+1] = *(const float4*)(g + 4);
    }
}
__device__ __forceinline__ uint32_t pack2(__nv_bfloat16 a, __nv_bfloat16 b){
    __nv_bfloat162 h; h.x = a; h.y = b;
    return *(uint32_t*)&h;
}
__device__ __forceinline__ void stsA(uint32_t sstage, int tid, const float4* pa){
    #pragma unroll
    for (int t = 0; t < 2; t++){
        int idx = tid + t*256;
        int row = idx >> 2, seg = idx & 3;
        float4 v0 = pa[2*t], v1 = pa[2*t+1];
        __nv_bfloat16 h0 = __float2bfloat16(v0.x), h1 = __float2bfloat16(v0.y);
        __nv_bfloat16 h2 = __float2bfloat16(v0.z), h3 = __float2bfloat16(v0.w);
        __nv_bfloat16 h4 = __float2bfloat16(v1.x), h5 = __float2bfloat16(v1.y);
        __nv_bfloat16 h6 = __float2bfloat16(v1.z), h7 = __float2bfloat16(v1.w);
        uint4 hv;
        hv.x = pack2(h0, h1); hv.y = pack2(h2, h3);
        hv.z = pack2(h4, h5); hv.w = pack2(h6, h7);
        uint4 lv;
        lv.x = pack2(__float2bfloat16(v0.x - __bfloat162float(h0)),
                     __float2bfloat16(v0.y - __bfloat162float(h1)));
        lv.y = pack2(__float2bfloat16(v0.z - __bfloat162float(h2)),
                     __float2bfloat16(v0.w - __bfloat162float(h3)));
        lv.z = pack2(__float2bfloat16(v1.x - __bfloat162float(h4)),
                     __float2bfloat16(v1.y - __bfloat162float(h5)));
        lv.w = pack2(__float2bfloat16(v1.z - __bfloat162float(h6)),
                     __float2bfloat16(v1.w - __bfloat162float(h7)));
        uint32_t dhi = sstage + row*80 + seg*16;
        asm volatile("st.shared.v4.b32 [%0], {%1,%2,%3,%4};"
                     :: "r"(dhi), "r"(hv.x), "r"(hv.y), "r"(hv.z), "r"(hv.w) : "memory");
        asm volatile("st.shared.v4.b32 [%0], {%1,%2,%3,%4};"
                     :: "r"(dhi + ARR_BYTES), "r"(lv.x), "r"(lv.y), "r"(lv.z), "r"(lv.w) : "memory");
    }
}

__global__ __launch_bounds__(256,2) void gemm_mma(
    const float* __restrict__ A,
    const __nv_bfloat16* __restrict__ Bhi, const __nv_bfloat16* __restrict__ Blo,
    const float* __restrict__ bias, float* __restrict__ C)
{
    extern __shared__ char smem[];
    uint32_t sb = smem_u32(smem);
    const int tid  = threadIdx.x;
    const int lane = tid & 31, warp = tid >> 5;
    const int wm64 = (warp >> 2) * 64, wn32 = (warp & 3) * 32;
    const int grp  = lane >> 2,  q2   = (lane & 3) * 2;
    const int n0 = blockIdx.x * 128, m0 = blockIdx.y * 128;
    const int lrow = (lane & 7) + ((lane >> 3) & 1) * 8;
    const int lcol = (lane >> 4) * 8;

    float acc[4][4][4];
    #pragma unroll
    for (int i=0;i<4;i++)
        #pragma unroll
        for (int j=0;j<4;j++)
            #pragma unroll
            for (int r=0;r<4;r++) acc[i][j][r]=0.f;

    float4 pa[4];
    prefetchA(A, m0, 0, tid, pa);
    loadB_async(Bhi, Blo, n0, 0, sb, tid);
    asm volatile("cp.async.commit_group;" ::: "memory");
    stsA(sb, tid, pa);
    prefetchA(A, m0, 32, tid, pa);
    loadB_async(Bhi, Blo, n0, 32, sb + STAGE_BYTES, tid);
    asm volatile("cp.async.commit_group;" ::: "memory");
    stsA(sb + STAGE_BYTES, tid, pa);
    prefetchA(A, m0, 64, tid, pa);

    for (int c = 0; c < 16; c++){
        if (c < 15) asm volatile("cp.async.wait_group 1;" ::: "memory");
        else        asm volatile("cp.async.wait_group 0;" ::: "memory");
        __syncthreads();

        const uint32_t st = sb + (c & 1)*STAGE_BYTES;
        const uint32_t aBase = st + (wm64 + lrow)*80 + lcol*2;
        const uint32_t bBase = st + 2*ARR_BYTES + (wn32 + lrow)*80 + lcol*2;

        #pragma unroll
        for (int pass = 0; pass < 3; pass++){
            const uint32_t aOff = aBase + ((pass == 1) ? ARR_BYTES : 0);
            const uint32_t bOff = bBase + ((pass == 2) ? ARR_BYTES : 0);
            #pragma unroll
            for (int ks = 0; ks < 2; ks++){
                const uint32_t kb = ks*32;
                uint32_t aq[4][4], bq[2][4];
                #pragma unroll
                for (int mt = 0; mt < 4; mt++)
                    ldsm4(aq[mt], aOff + mt*16*80 + kb);
                ldsm4(bq[0], bOff + kb);
                ldsm4(bq[1], bOff + 16*80 + kb);
                #pragma unroll
                for (int mt = 0; mt < 4; mt++)
                    #pragma unroll
                    for (int nt = 0; nt < 4; nt++)
                        mma16816(acc[mt][nt], aq[mt],
                                 bq[nt>>1][nt&1], bq[nt>>1][2+(nt&1)]);
            }
        }
        __syncthreads();
        if (c + 2 < 16){
            uint32_t dst = sb + (c & 1)*STAGE_BYTES;
            loadB_async(Bhi, Blo, n0, (c+2)*32, dst, tid);
            asm volatile("cp.async.commit_group;" ::: "memory");
            stsA(dst, tid, pa);
            if (c + 3 < 16) prefetchA(A, m0, (c+3)*32, tid, pa);
        }
    }

    #pragma unroll
    for (int mt = 0; mt < 4; mt++){
        #pragma unroll
        for (int nt = 0; nt < 4; nt++){
            int r   = m0 + wm64 + mt*16 + grp;
            int col = n0 + wn32 + nt*8 + q2;
            float b0 = bias[col], b1 = bias[col+1];
            float2 v0 = make_float2(acc[mt][nt][0] + b0, acc[mt][nt][1] + b1);
            float2 v1 = make_float2(acc[mt][nt][2] + b0, acc[mt][nt][3] + b1);
            *(float2*)(C + (size_t)r*512 + col)     = v0;
            *(float2*)(C + (size_t)(r+8)*512 + col) = v1;
        }
    }
}

// ---------------- fused wavelet (q and k in one launch, grid.z = 2) ----------------
__global__ __launch_bounds__(256) void wavelet_qk(
    const float* __restrict__ qx, float* __restrict__ qd, float* __restrict__ qs,
    const float* __restrict__ kx, float* __restrict__ kd, float* __restrict__ ks,
    const float* __restrict__ ecd, const float* __restrict__ ecs,
    int Lh, int total)
{
    __shared__ float wd[16][8], ws[16][8];
    int tid = threadIdx.x;
    if (tid < 128){ ((float*)wd)[tid] = ecd[tid]; ((float*)ws)[tid] = ecs[tid]; }
    __syncthreads();
    int idx = blockIdx.x*256 + tid;
    if (idx >= total) return;
    const float* x = blockIdx.z ? kx : qx;
    float* d = blockIdx.z ? kd : qd;
    float* s = blockIdx.z ? ks : qs;
    int c = idx & 63;
    int j = (idx >> 6) % Lh;
    int b = idx / (Lh << 6);
    const float* xe = x + (((size_t)b*(Lh<<1) + 2*j)*64 + c)*8;
    float xa[16];
    *(float4*)(xa)    = *(const float4*)(xe);
    *(float4*)(xa+4)  = *(const float4*)(xe+4);
    *(float4*)(xa+8)  = *(const float4*)(xe+512);
    *(float4*)(xa+12) = *(const float4*)(xe+516);
    float dv[8], sv[8];
    #pragma unroll
    for (int k2=0;k2<8;k2++){ dv[k2]=0.f; sv[k2]=0.f; }
    #pragma unroll
    for (int t=0;t<16;t++){
        float xv = xa[t];
        #pragma unroll
        for (int k2=0;k2<8;k2++){ dv[k2] += xv*wd[t][k2]; sv[k2] += xv*ws[t][k2]; }
    }
    float* dp = d + (size_t)idx*8;
    float* sp = s + (size_t)idx*8;
    *(float4*)(dp)   = make_float4(dv[0],dv[1],dv[2],dv[3]);
    *(float4*)(dp+4) = make_float4(dv[4],dv[5],dv[6],dv[7]);
    *(float4*)(sp)   = make_float4(sv[0],sv[1],sv[2],sv[3]);
    *(float4*)(sp+4) = make_float4(sv[4],sv[5],sv[6],sv[7]);
}

// ---------------- forward DFT (shallow levels) ----------------
__global__ __launch_bounds__(256) void dft_kernel(
    const float* __restrict__ t0, const float* __restrict__ t1,
    const float* __restrict__ t2, const float* __restrict__ t3,
    float* __restrict__ S, int Lh, int m)
{
    __shared__ float2 tw2[512];
    __shared__ float pr[16][128], pi[16][128];
    const int tid = threadIdx.x;
    const int b = blockIdx.x, tensor = blockIdx.y, ck0 = blockIdx.z * 128;
    for (int r = tid; r < Lh; r += 256){
        float sv, cv;
        sincosf(6.283185307179586f * ((float)r / (float)Lh), &sv, &cv);
        tw2[r] = make_float2(cv, sv);
    }
    __syncthreads();
    const float* X = (tensor==0) ? t0 : (tensor==1) ? t1 : (tensor==2) ? t2 : t3;
    const int col  = tid & 127;
    const int half = tid >> 7;
    const int Lh2  = Lh >> 1;
    const float* p = X + ((size_t)b*Lh + (size_t)half*Lh2)*512 + ck0 + col;
    float ar[16], ai[16];
    #pragma unroll
    for (int f=0; f<16; f++){ ar[f]=0.f; ai[f]=0.f; }
    for (int li=0; li<Lh2; li++){
        const int l = half*Lh2 + li;
        float xv = p[(size_t)li*512];
        int r = 0;
        #pragma unroll
        for (int f=0; f<16; f++){
            float2 t = tw2[r];
            ar[f] += xv * t.x;
            ai[f] += xv * t.y;
            r += l; if (r >= Lh) r -= Lh;
        }
    }
    if (half){
        #pragma unroll
        for (int f=0; f<16; f++){ pr[f][col]=ar[f]; pi[f][col]=ai[f]; }
    }
    __syncthreads();
    if (!half){
        float* out = S + (((size_t)b*4 + tensor)*2*16)*512 + ck0 + col;
        for (int f=0; f<m; f++){
            out[(size_t)f*512]        =  ar[f] + pr[f][col];
            out[8192 + (size_t)f*512] = -(ai[f] + pi[f][col]);
        }
    }
}

// ---------------- mid (shallow) ----------------
__global__ __launch_bounds__(256) void mid_kernel(const float* __restrict__ S,
    float* __restrict__ O, int m)
{
    __shared__ float Sqr[64][16], Sqi[64][16], Skr[64][16], Ski[64][16];
    __shared__ float QKr[16][17], QKi[16][17];
    const int tid = threadIdx.x;
    const int b = blockIdx.x >> 3, h = blockIdx.x & 7;
    const int which = blockIdx.y;

    const float* base = S + (size_t)(b*4 + which*2)*2*16*512;
    for (int idx = tid; idx < 64*16; idx += 256){
        int e = idx >> 4, f = idx & 15;
        size_t o = (size_t)f*512 + e*8 + h;
        Sqr[e][f] = base[o];
        Sqi[e][f] = base[o + 8192];
        Skr[e][f] = base[o + 16384];
        Ski[e][f] = base[o + 24576];
    }
    __syncthreads();

    if (tid < m*m){
        int x = tid / m, y = tid - (tid/m)*m;
        float sr=0.f, sim=0.f;
        #pragma unroll 8
        for (int e=0;e<64;e++){
            float qr=Sqr[e][x], qi=Sqi[e][x];
            float kr=Skr[e][y], ki=Ski[e][y];
            sr  += qr*kr - qi*ki;
            sim += qr*ki + qi*kr;
        }
        float txx = tanhf(sr);
        float tyy = tanf(sim);
        float tx2=txx*txx, ty2=tyy*tyy;
        float den = 1.0f + tx2*ty2;
        QKr[x][y] = txx*(1.0f+ty2)/den;
        QKi[x][y] = tyy*(1.0f-tx2)/den;
    }
    __syncthreads();

    float* ob = O + (size_t)(b*2 + which)*2*16*512;
    for (int t = tid; t < 64*m; t += 256){
        int x = t % m, e = t / m;
        float orr=0.f, oii=0.f;
        for (int y=0;y<m;y++){
            float ar=QKr[x][y], ai2=QKi[x][y];
            float br=Skr[e][y], bi=Ski[e][y];
            orr += ar*br - ai2*bi;
            oii += ar*bi + ai2*br;
        }
        size_t o = (size_t)x*512 + e*8 + h;
        ob[o]        = orr;
        ob[o + 8192] = oii;
    }
}

// ---------------- inverse DFT + fused add (shallow) ----------------
__global__ __launch_bounds__(256) void idft_kernel(const float* __restrict__ O,
    float* __restrict__ Us, float* __restrict__ Ud,
    int Lh, int m, float scale, int rows)
{
    __shared__ float twc[512], tws[512];
    __shared__ float Osm[2][2][16][128];
    const int tid = threadIdx.x;
    const int b = blockIdx.x, ck0 = blockIdx.y * 128;
    for (int r = tid; r < Lh; r += 256){
        float sv, cv;
        sincosf(6.283185307179586f * ((float)r / (float)Lh), &sv, &cv);
        twc[r]=cv; tws[r]=sv;
    }
    for (int idx = tid; idx < 2*2*16*128; idx += 256){
        int w    = idx >> 12;
        int rem  = idx & 4095;
        int reim = rem >> 11;
        int f    = (rem >> 7) & 15;
        int col  = rem & 127;
        Osm[w][reim][f][col] =
            O[(size_t)((b*2 + w)*2 + reim)*8192 + (size_t)f*512 + ck0 + col];
    }
    __syncthreads();
    const int l0 = blockIdx.z * rows;
    for (int t = tid; t < rows*128; t += 256){
        int lr = t >> 7, col = t & 127;
        int l = l0 + lr;
        float as = Osm[0][0][0][col];
        float ad = Osm[1][0][0][col];
        int r = 0;
        for (int f=1; f<m; f++){
            r += l; if (r >= Lh) r -= Lh;
            float c = twc[r], s = tws[r];
            as += 2.0f*(Osm[0][0][f][col]*c - Osm[0][1][f][col]*s);
            ad += 2.0f*(Osm[1][0][f][col]*c - Osm[1][1][f][col]*s);
        }
        size_t oi = ((size_t)b*Lh + l)*512 + ck0 + col;
        float usv = as * scale;
        Us[oi] = usv;
        Ud[oi] = ad * scale + usv;
    }
}

// ---------------- DEEP: levels 3..8 (Lh 64..2), one block per b ----------------
#define DTH 1024
#define DSCR 262144   // per-b floats in g_dq / g_dk
__global__ __launch_bounds__(DTH) void deep_kernel(
    const float* __restrict__ qin, const float* __restrict__ kin,   // packed b*128*512
    float* __restrict__ us, float* __restrict__ ud,
    float* __restrict__ qscr, float* __restrict__ kscr,
    float* __restrict__ S, float* __restrict__ O,
    const float* __restrict__ ecd, const float* __restrict__ ecs)
{
    const int b = blockIdx.x, tid = threadIdx.x;
    __shared__ float wd[16][8], ws[16][8];
    __shared__ float2 tw2[64];
    __shared__ float sq[2][64][16], sk[2][64][16];
    __shared__ float qkr[16][17], qki[16][17];
    if (tid < 128){ ((float*)wd)[tid]=ecd[tid]; ((float*)ws)[tid]=ecs[tid]; }

    float* qA  = qscr + (size_t)b*DSCR;
    float* qB  = qA + 32768;
    float* dql = qA + 65536;
    float* kAa = kscr + (size_t)b*DSCR;
    float* kBb = kAa + 32768;
    float* dkl = kAa + 65536;
    float* Sb  = S + (size_t)b*65536;
    float* Ob  = O + (size_t)b*32768;

    const float* qc = qin + (size_t)b*65536;
    const float* kc = kin + (size_t)b*65536;
    float* qn = qA; float* kn = kAa;
    int L = 128;
    #pragma unroll 1
    for (int lev = 3; lev <= 8; lev++){
        const int Lh = L >> 1;
        const int m  = (Lh>>1) < 16 ? (Lh>>1) : 16;
        __syncthreads();                       // guards tw2/wd reuse & buffer swap
        if (tid < Lh){
            float sv, cv;
            sincosf(6.283185307179586f*((float)tid/(float)Lh), &sv, &cv);
            tw2[tid] = make_float2(cv, sv);
        }
        __syncthreads();                       // wd (first iter) + tw2 ready

        // ---- wavelet both tensors ----
        const int witems = Lh*64;
        for (int it = tid; it < 2*witems; it += DTH){
            int tens = (it >= witems);
            int idx  = tens ? it - witems : it;
            int c = idx & 63, j = idx >> 6;
            const float* xe = (tens ? kc : qc) + (size_t)(2*j)*512 + c*8;
            float xa[16];
            *(float4*)(xa)    = *(const float4*)(xe);
            *(float4*)(xa+4)  = *(const float4*)(xe+4);
            *(float4*)(xa+8)  = *(const float4*)(xe+512);
            *(float4*)(xa+12) = *(const float4*)(xe+516);
            float dv[8], sv8[8];
            #pragma unroll
            for (int k2=0;k2<8;k2++){ dv[k2]=0.f; sv8[k2]=0.f; }
            #pragma unroll
            for (int t=0;t<16;t++){
                float xv = xa[t];
                #pragma unroll
                for (int k2=0;k2<8;k2++){ dv[k2] += xv*wd[t][k2]; sv8[k2] += xv*ws[t][k2]; }
            }
            float* dp = (tens ? dkl : dql) + (size_t)idx*8;
            float* sp = (tens ? kn  : qn ) + (size_t)idx*8;
            *(float4*)(dp)   = make_float4(dv[0],dv[1],dv[2],dv[3]);
            *(float4*)(dp+4) = make_float4(dv[4],dv[5],dv[6],dv[7]);
            *(float4*)(sp)   = make_float4(sv8[0],sv8[1],sv8[2],sv8[3]);
            *(float4*)(sp+4) = make_float4(sv8[4],sv8[5],sv8[6],sv8[7]);
        }
        __syncthreads();

        // ---- forward DFT ----
        for (int it = tid; it < 2048; it += DTH){
            int tensor = it >> 9, col = it & 511;
            const float* p = ((tensor==0) ? dql : (tensor==1) ? dkl :
                              (tensor==2) ? (const float*)qn : (const float*)kn) + col;
            float ar[16], ai[16];
            #pragma unroll
            for (int f=0;f<16;f++){ ar[f]=0.f; ai[f]=0.f; }
            for (int l=0; l<Lh; l++){
                float xv = p[(size_t)l*512];
                int r = 0;
                #pragma unroll
                for (int f=0;f<16;f++){
                    float2 t = tw2[r];
                    ar[f] += xv*t.x; ai[f] += xv*t.y;
                    r += l; if (r >= Lh) r -= Lh;
                }
            }
            for (int f=0; f<m; f++){
                Sb[(size_t)((tensor*2+0)*16+f)*512 + col] =  ar[f];
                Sb[(size_t)((tensor*2+1)*16+f)*512 + col] = -ai[f];
            }
        }
        __syncthreads();

        // ---- mid: loop (which, h) ----
        for (int wh = 0; wh < 16; wh++){
            const int w = wh >> 3, h = wh & 7;
            for (int it = tid; it < 4096; it += DTH){
                int qk = it >> 11, ri = (it >> 10) & 1;
                int e = (it >> 4) & 63, f = it & 15;
                int tensor = w*2 + qk;
                float v = (f < m) ? Sb[(size_t)((tensor*2+ri)*16+f)*512 + e*8 + h] : 0.f;
                if (qk == 0) sq[ri][e][f] = v; else sk[ri][e][f] = v;
            }
            __syncthreads();
            if (tid < m*m){
                int x = tid / m, y = tid - (tid/m)*m;
                float sr=0.f, sim=0.f;
                #pragma unroll 8
                for (int e=0;e<64;e++){
                    float qr=sq[0][e][x], qi=sq[1][e][x];
                    float kr=sk[0][e][y], ki=sk[1][e][y];
                    sr  += qr*kr - qi*ki;
                    sim += qr*ki + qi*kr;
                }
                float txx = tanhf(sr);
                float tyy = tanf(sim);
                float tx2=txx*txx, ty2=tyy*tyy;
                float den = 1.0f + tx2*ty2;
                qkr[x][y] = txx*(1.0f+ty2)/den;
                qki[x][y] = tyy*(1.0f-tx2)/den;
            }
            __syncthreads();
            for (int it = tid; it < 64*m; it += DTH){
                int x2 = it % m, e = it / m;
                float orr=0.f, oii=0.f;
                for (int y=0;y<m;y++){
                    float ar2=qkr[x2][y], ai2=qki[x2][y];
                    float br=sk[0][e][y], bi=sk[1][e][y];
                    orr += ar2*br - ai2*bi;
                    oii += ar2*bi + ai2*br;
                }
                Ob[(size_t)((w*2+0)*16+x2)*512 + e*8 + h] = orr;
                Ob[(size_t)((w*2+1)*16+x2)*512 + e*8 + h] = oii;
            }
            __syncthreads();
        }

        // ---- inverse DFT + write Us/Ud ----
        if (tid < 512){
            const int col = tid;
            float Or2[2][16], Oi2[2][16];
            for (int w2=0; w2<2; w2++)
                for (int f=0; f<m; f++){
                    Or2[w2][f] = Ob[(size_t)((w2*2+0)*16+f)*512 + col];
                    Oi2[w2][f] = Ob[(size_t)((w2*2+1)*16+f)*512 + col];
                }
            float scale = 1.0f/(4096.0f*(float)Lh);
            size_t ub = doffs(lev) + ((size_t)b*Lh)*512 + col;
            for (int l=0; l<Lh; l++){
                float as = Or2[0][0], ad = Or2[1][0];
                int r = 0;
                for (int f=1; f<m; f++){
                    r += l; if (r >= Lh) r -= Lh;
                    float c2 = tw2[r].x, s2 = tw2[r].y;
                    as += 2.f*(Or2[0][f]*c2 - Oi2[0][f]*s2);
                    ad += 2.f*(Or2[1][f]*c2 - Oi2[1][f]*s2);
                }
                float usv = as*scale;
                us[ub + (size_t)l*512] = usv;
                ud[ub + (size_t)l*512] = ad*scale + usv;
            }
        }
        // swap buffers
        qc = qn; kc = kn;
        qn = (qn == qA)  ? qB  : qA;
        kn = (kn == kAa) ? kBb : kAa;
        L = Lh;
    }
}

// ---------------- DEEP recon: steps lev 9..4 (Lv 1 -> 64), one block per b ----------------
__global__ __launch_bounds__(512) void deep_recon(
    const float* __restrict__ us, const float* __restrict__ ud,
    const float* __restrict__ rce, const float* __restrict__ rco,
    float* __restrict__ vscr, float* __restrict__ vout)
{
    const int b = blockIdx.x, tid = threadIdx.x;
    __shared__ float we[16][8], wo[16][8];
    if (tid < 128){ ((float*)we)[tid] = rce[tid]; ((float*)wo)[tid] = rco[tid]; }
    float* vA = vscr + (size_t)b*DSCR;
    float* vc = vA; float* vn = vA + 32768;
    if (tid < 512) vc[tid] = 0.f;
    __syncthreads();
    int Lv = 1;
    for (int lev = 9; lev >= 4; lev--){
        size_t o = doffs(lev) + (size_t)b*Lv*512;
        int items = Lv*64;
        for (int it = tid; it < items; it += 512){
            int c = it & 63, l = it >> 6;
            const float* vp = vc + (size_t)it*8;
            const float* up = us + o + (size_t)it*8;
            const float* dp = ud + o + (size_t)it*8;
            float w[16];
            #pragma unroll
            for (int t=0;t<8;t++) w[t]   = vp[t] + up[t];
            #pragma unroll
            for (int t=0;t<8;t++) w[8+t] = dp[t];
            float ev[8], ov[8];
            #pragma unroll
            for (int k2=0;k2<8;k2++){ ev[k2]=0.f; ov[k2]=0.f; }
            #pragma unroll
            for (int t=0;t<16;t++){
                float xv = w[t];
                #pragma unroll
                for (int k2=0;k2<8;k2++){ ev[k2] += xv*we[t][k2]; ov[k2] += xv*wo[t][k2]; }
            }
            float* op = vn + (size_t)(2*l)*512 + c*8;
            *(float4*)(op)     = make_float4(ev[0],ev[1],ev[2],ev[3]);
            *(float4*)(op+4)   = make_float4(ev[4],ev[5],ev[6],ev[7]);
            *(float4*)(op+512) = make_float4(ov[0],ov[1],ov[2],ov[3]);
            *(float4*)(op+516) = make_float4(ov[4],ov[5],ov[6],ov[7]);
        }
        __syncthreads();
        float* t = vc; vc = vn; vn = t;
        Lv <<= 1;
    }
    // vc holds 64*512 per b -> write packed
    for (int it = tid; it < 32768; it += 512)
        vout[(size_t)b*32768 + it] = vc[it];
}

// ---------------- recon (shallow) ----------------
__global__ __launch_bounds__(256) void recon_kernel(const float* __restrict__ v,
    const float* __restrict__ Us, const float* __restrict__ Ud,
    const float* __restrict__ rce, const float* __restrict__ rco,
    float* __restrict__ outv, int Lv, int total)
{
    __shared__ float we[16][8], wo[16][8];
    int tid = threadIdx.x;
    if (tid < 128){ ((float*)we)[tid] = rce[tid]; ((float*)wo)[tid] = rco[tid]; }
    __syncthreads();
    int idx = blockIdx.x*256 + tid;
    if (idx >= total) return;
    int c = idx & 63;
    int l = (idx >> 6) % Lv;
    int b = idx / (Lv << 6);
    const float* vp = v  + (size_t)idx*8;
    const float* up = Us + (size_t)idx*8;
    const float* dp = Ud + (size_t)idx*8;
    float w[16];
    #pragma unroll
    for (int t=0;t<8;t++) w[t]   = vp[t] + up[t];
    #pragma unroll
    for (int t=0;t<8;t++) w[8+t] = dp[t];
    float ev[8], ov[8];
    #pragma unroll
    for (int k2=0;k2<8;k2++){ ev[k2]=0.f; ov[k2]=0.f; }
    #pragma unroll
    for (int t=0;t<16;t++){
        float xv = w[t];
        #pragma unroll
        for (int k2=0;k2<8;k2++){ ev[k2] += xv*we[t][k2]; ov[k2] += xv*wo[t][k2]; }
    }
    float* op = outv + (((size_t)b*(Lv<<1) + 2*l)*64 + c)*8;
    *(float4*)(op)     = make_float4(ev[0],ev[1],ev[2],ev[3]);
    *(float4*)(op+4)   = make_float4(ev[4],ev[5],ev[6],ev[7]);
    *(float4*)(op+512) = make_float4(ov[0],ov[1],ov[2],ov[3]);
    *(float4*)(op+516) = make_float4(ov[4],ov[5],ov[6],ov[7]);
}

// ---------------- orchestration ----------------
extern "C" void kernel_launch(void* const* d_in, const int* in_sizes, int n_in,
                              void* d_out, int out_size)
{
    (void)in_sizes; (void)n_in; (void)out_size;
    const float* q     = (const float*)d_in[0];
    const float* k     = (const float*)d_in[1];
    const float* Lq_w  = (const float*)d_in[3];
    const float* Lq_b  = (const float*)d_in[4];
    const float* Lk_w  = (const float*)d_in[5];
    const float* Lk_b  = (const float*)d_in[6];
    const float* out_w = (const float*)d_in[9];
    const float* out_b = (const float*)d_in[10];
    const float* ec_s  = (const float*)d_in[11];
    const float* ec_d  = (const float*)d_in[12];
    const float* rc_e  = (const float*)d_in[13];
    const float* rc_o  = (const float*)d_in[14];
    float* outp = (float*)d_out;

    float *bufA,*bufB,*kA,*kB,*dq,*dk,*us,*ud,*S,*O;
    __nv_bfloat16 *Wthi,*Wtlo,*W2hi,*W2lo,*W3hi,*W3lo;
    cudaGetSymbolAddress((void**)&bufA, g_bufA);
    cudaGetSymbolAddress((void**)&bufB, g_bufB);
    cudaGetSymbolAddress((void**)&kA,   g_kA);
    cudaGetSymbolAddress((void**)&kB,   g_kB);
    cudaGetSymbolAddress((void**)&dq,   g_dq);
    cudaGetSymbolAddress((void**)&dk,   g_dk);
    cudaGetSymbolAddress((void**)&us,   g_Us);
    cudaGetSymbolAddress((void**)&ud,   g_Ud);
    cudaGetSymbolAddress((void**)&S,    g_S);
    cudaGetSymbolAddress((void**)&O,    g_O);
    cudaGetSymbolAddress((void**)&Wthi, g_Wthi);
    cudaGetSymbolAddress((void**)&Wtlo, g_Wtlo);
    cudaGetSymbolAddress((void**)&W2hi, g_W2hi);
    cudaGetSymbolAddress((void**)&W2lo, g_W2lo);
    cudaGetSymbolAddress((void**)&W3hi, g_W3hi);
    cudaGetSymbolAddress((void**)&W3lo, g_W3lo);

    cudaFuncSetAttribute(gemm_mma, cudaFuncAttributeMaxDynamicSharedMemorySize, GEMM_SMEM);

    dim3 gG(4,128);

    size_t offs[10]; size_t off=0;
    { int L = 1024;
      for (int i=0;i<10;i++){ int Lh = L >> 1; offs[i] = off; off += (size_t)16*Lh*512; L = Lh; } }

    // 1: all three weight conversions; 2: level-9 zeros; 3,4: GEMMs (#4 = ncu target)
    convW3_kernel<<<dim3(16,16,3),256>>>(Lq_w, Lk_w, out_w,
                                         Wthi, Wtlo, W2hi, W2lo, W3hi, W3lo);
    zero2_kernel<<<32,256>>>(us+offs[9], ud+offs[9], 16*1*512);
    gemm_mma<<<gG,256,GEMM_SMEM>>>(q, Wthi, Wtlo, Lq_b, bufA);
    gemm_mma<<<gG,256,GEMM_SMEM>>>(k, W2hi, W2lo, Lk_b, kA);

    // shallow levels 0..2 (Lh = 512, 256, 128)
    float *qc=bufA,*qn=bufB,*kc=kA,*kn=kB;
    int L = 1024;
    for (int i=0;i<3;i++){
        int Lh = L >> 1;
        int m  = 16;
        int total = 16*Lh*64;
        int blocks = (total + 255)/256;
        wavelet_qk<<<dim3(blocks,1,2),256>>>(qc, dq, qn, kc, dk, kn, ec_d, ec_s, Lh, total);
        dft_kernel<<<dim3(16,4,4),256>>>(dq, dk, qn, kn, S, Lh, m);
        mid_kernel<<<dim3(128,2),256>>>(S, O, m);
        float inv_scale = 1.0f/(4096.0f*(float)Lh);
        int lsplit = Lh/64;
        idft_kernel<<<dim3(16,4,lsplit),256>>>(O, us+offs[i], ud+offs[i], Lh, m, inv_scale, 64);
        float* t; t=qc; qc=qn; qn=t;  t=kc; kc=kn; kn=t;
        L = Lh;
    }
    // after 3 swaps: qc = bufB, kc = kB (level-2 outputs, Lh=128 packing)

    // deep levels 3..8 in one kernel (scratch reuses g_dq/g_dk; spectra in g_S/g_O)
    deep_kernel<<<16,DTH>>>(qc, kc, us, ud, dq, dk, S, O, ec_d, ec_s);

    // deep recon (Lv 1 -> 64) -> bufA (packed b*64*512)
    deep_recon<<<16,512>>>(us, ud, rc_e, rc_o, dq, bufA);

    // shallow recon i = 3..0
    float *vc=bufA, *vn=bufB;
    int Lv = 64;
    for (int i=3;i>=0;i--){
        int total = 16*Lv*64;
        recon_kernel<<<(total+255)/256,256>>>(vc, us+offs[i], ud+offs[i],
                                              rc_e, rc_o, vn, Lv, total);
        float* t=vc; vc=vn; vn=t;
        Lv <<= 1;
    }
    // 4 swaps -> final v in bufA

    gemm_mma<<<gG,256,GEMM_SMEM>>>(vc, W3hi, W3lo, out_b, outp);
}

// round 15
// speedup vs baseline: 1.5037x; 1.5037x over previous
#include <cuda_runtime.h>
#include <cuda_bf16.h>
#include <math.h>
#include <stdint.h>

// Problem constants
#define NB   16
#define NSEQ 1024
#define CK   512          // C*K

// -------- scratch (device globals; no allocation allowed) --------
__device__ float g_bufA[NB*NSEQ*CK];
__device__ float g_bufB[NB*NSEQ*CK];
__device__ float g_kA[NB*NSEQ*CK];
__device__ float g_kB[NB*NSEQ*CK];
__device__ float g_dq[NB*512*CK];     // wavelet detail q; later deep_recon scratch
__device__ float g_dk[NB*512*CK];     // wavelet detail k
__device__ float g_Us[NB*1023*CK];
__device__ float g_Ud[NB*1023*CK];
__device__ float g_S[NB*4*2*16*CK];   // spectra
__device__ float g_O[NB*2*2*16*CK];   // post-attn spectra (shallow only)
__device__ __nv_bfloat16 g_Wthi[CK*CK];
__device__ __nv_bfloat16 g_Wtlo[CK*CK];
__device__ __nv_bfloat16 g_W2hi[CK*CK];
__device__ __nv_bfloat16 g_W2lo[CK*CK];
__device__ __nv_bfloat16 g_W3hi[CK*CK];
__device__ __nv_bfloat16 g_W3lo[CK*CK];

__device__ __forceinline__ uint32_t smem_u32(const void* p){
    uint32_t a;
    asm("{ .reg .u64 t; cvta.to.shared.u64 t, %1; cvt.u32.u64 %0, t; }" : "=r"(a) : "l"(p));
    return a;
}
__device__ __forceinline__ size_t doffs(int lev){
    return (size_t)16*512*(1024 - (1024 >> lev));
}

// ---- convW3: three W fp32 [K,N] -> transposed bf16 hi/lo pairs (one launch) ----
__global__ __launch_bounds__(256) void convW3_kernel(
    const float* __restrict__ W0, const float* __restrict__ W1, const float* __restrict__ W2,
    __nv_bfloat16* h0, __nv_bfloat16* l0,
    __nv_bfloat16* h1, __nv_bfloat16* l1,
    __nv_bfloat16* h2, __nv_bfloat16* l2)
{
    __shared__ float t[32][33];
    int z = blockIdx.z;
    const float* W = (z==0) ? W0 : (z==1) ? W1 : W2;
    __nv_bfloat16* hi = (z==0) ? h0 : (z==1) ? h1 : h2;
    __nv_bfloat16* lo = (z==0) ? l0 : (z==1) ? l1 : l2;
    int bx = blockIdx.x, by = blockIdx.y;
    int tx = threadIdx.x & 31, ty = threadIdx.x >> 5;
    for (int i = ty; i < 32; i += 8)
        t[i][tx] = W[(size_t)(bx*32 + i)*512 + by*32 + tx];
    __syncthreads();
    for (int i = ty; i < 32; i += 8){
        float v = t[tx][i];
        __nv_bfloat16 h = __float2bfloat16(v);
        size_t o = (size_t)(by*32 + i)*512 + bx*32 + tx;
        hi[o] = h;
        lo[o] = __float2bfloat16(v - __bfloat162float(h));
    }
}

__global__ void zero2_kernel(float* p1, float* p2, int n){
    int i = blockIdx.x*blockDim.x + threadIdx.x;
    if (i < n){ p1[i] = 0.f; p2[i] = 0.f; }
}

// ================= tensor-core GEMM (R11-proven mainloop) =================
#define STAGE_BYTES 40960
#define ARR_BYTES   10240
#define GEMM_SMEM   (2*STAGE_BYTES)

__device__ __forceinline__ void mma16816(float* d, const uint32_t* a, uint32_t b0, uint32_t b1){
    asm volatile(
        "mma.sync.aligned.m16n8k16.row.col.f32.bf16.bf16.f32 "
        "{%0,%1,%2,%3}, {%4,%5,%6,%7}, {%8,%9}, {%0,%1,%2,%3};"
        : "+f"(d[0]), "+f"(d[1]), "+f"(d[2]), "+f"(d[3])
        : "r"(a[0]), "r"(a[1]), "r"(a[2]), "r"(a[3]), "r"(b0), "r"(b1));
}
__device__ __forceinline__ void ldsm4(uint32_t* r, uint32_t addr){
    asm volatile("ldmatrix.sync.aligned.m8n8.x4.shared.b16 {%0,%1,%2,%3}, [%4];"
        : "=r"(r[0]), "=r"(r[1]), "=r"(r[2]), "=r"(r[3]) : "r"(addr));
}
__device__ __forceinline__ void loadB_async(
    const __nv_bfloat16* __restrict__ Bhi, const __nv_bfloat16* __restrict__ Blo,
    int n0, int k0, uint32_t sstage, int tid)
{
    #pragma unroll
    for (int t = 4; t < 8; t++){
        const int arr = t >> 1;
        const int row = (t & 1)*64 + (tid >> 2);
        const int seg = tid & 3;
        const __nv_bfloat16* g = ((arr == 2) ? Bhi : Blo) + (size_t)(n0 + row)*512 + k0 + seg*8;
        uint32_t d = sstage + arr*ARR_BYTES + row*80 + seg*16;
        asm volatile("cp.async.cg.shared.global [%0], [%1], 16;" :: "r"(d), "l"(g));
    }
}
__device__ __forceinline__ void prefetchA(const float* __restrict__ A,
    int m0, int k0, int tid, float4* pa)
{
    #pragma unroll
    for (int t = 0; t < 2; t++){
        int idx = tid + t*256;
        int row = idx >> 2, seg = idx & 3;
        const float* g = A + (size_t)(m0 + row)*512 + k0 + seg*8;
        pa[2*t]   = *(const float4*)g;
        pa[2*t+1] = *(const float4*)(g + 4);
    }
}
__device__ __forceinline__ uint32_t pack2(__nv_bfloat16 a, __nv_bfloat16 b){
    __nv_bfloat162 h; h.x = a; h.y = b;
    return *(uint32_t*)&h;
}
__device__ __forceinline__ void stsA(uint32_t sstage, int tid, const float4* pa){
    #pragma unroll
    for (int t = 0; t < 2; t++){
        int idx = tid + t*256;
        int row = idx >> 2, seg = idx & 3;
        float4 v0 = pa[2*t], v1 = pa[2*t+1];
        __nv_bfloat16 h0 = __float2bfloat16(v0.x), h1 = __float2bfloat16(v0.y);
        __nv_bfloat16 h2 = __float2bfloat16(v0.z), h3 = __float2bfloat16(v0.w);
        __nv_bfloat16 h4 = __float2bfloat16(v1.x), h5 = __float2bfloat16(v1.y);
        __nv_bfloat16 h6 = __float2bfloat16(v1.z), h7 = __float2bfloat16(v1.w);
        uint4 hv;
        hv.x = pack2(h0, h1); hv.y = pack2(h2, h3);
        hv.z = pack2(h4, h5); hv.w = pack2(h6, h7);
        uint4 lv;
        lv.x = pack2(__float2bfloat16(v0.x - __bfloat162float(h0)),
                     __float2bfloat16(v0.y - __bfloat162float(h1)));
        lv.y = pack2(__float2bfloat16(v0.z - __bfloat162float(h2)),
                     __float2bfloat16(v0.w - __bfloat162float(h3)));
        lv.z = pack2(__float2bfloat16(v1.x - __bfloat162float(h4)),
                     __float2bfloat16(v1.y - __bfloat162float(h5)));
        lv.w = pack2(__float2bfloat16(v1.z - __bfloat162float(h6)),
                     __float2bfloat16(v1.w - __bfloat162float(h7)));
        uint32_t dhi = sstage + row*80 + seg*16;
        asm volatile("st.shared.v4.b32 [%0], {%1,%2,%3,%4};"
                     :: "r"(dhi), "r"(hv.x), "r"(hv.y), "r"(hv.z), "r"(hv.w) : "memory");
        asm volatile("st.shared.v4.b32 [%0], {%1,%2,%3,%4};"
                     :: "r"(dhi + ARR_BYTES), "r"(lv.x), "r"(lv.y), "r"(lv.z), "r"(lv.w) : "memory");
    }
}

__device__ __forceinline__ void gemm_body(
    const float* __restrict__ A,
    const __nv_bfloat16* __restrict__ Bhi, const __nv_bfloat16* __restrict__ Blo,
    const float* __restrict__ bias, float* __restrict__ C, char* smem)
{
    uint32_t sb = smem_u32(smem);
    const int tid  = threadIdx.x;
    const int lane = tid & 31, warp = tid >> 5;
    const int wm64 = (warp >> 2) * 64, wn32 = (warp & 3) * 32;
    const int grp  = lane >> 2,  q2   = (lane & 3) * 2;
    const int n0 = blockIdx.x * 128, m0 = blockIdx.y * 128;
    const int lrow = (lane & 7) + ((lane >> 3) & 1) * 8;
    const int lcol = (lane >> 4) * 8;

    float acc[4][4][4];
    #pragma unroll
    for (int i=0;i<4;i++)
        #pragma unroll
        for (int j=0;j<4;j++)
            #pragma unroll
            for (int r=0;r<4;r++) acc[i][j][r]=0.f;

    float4 pa[4];
    prefetchA(A, m0, 0, tid, pa);
    loadB_async(Bhi, Blo, n0, 0, sb, tid);
    asm volatile("cp.async.commit_group;" ::: "memory");
    stsA(sb, tid, pa);
    prefetchA(A, m0, 32, tid, pa);
    loadB_async(Bhi, Blo, n0, 32, sb + STAGE_BYTES, tid);
    asm volatile("cp.async.commit_group;" ::: "memory");
    stsA(sb + STAGE_BYTES, tid, pa);
    prefetchA(A, m0, 64, tid, pa);

    for (int c = 0; c < 16; c++){
        if (c < 15) asm volatile("cp.async.wait_group 1;" ::: "memory");
        else        asm volatile("cp.async.wait_group 0;" ::: "memory");
        __syncthreads();

        const uint32_t st = sb + (c & 1)*STAGE_BYTES;
        const uint32_t aBase = st + (wm64 + lrow)*80 + lcol*2;
        const uint32_t bBase = st + 2*ARR_BYTES + (wn32 + lrow)*80 + lcol*2;

        #pragma unroll
        for (int pass = 0; pass < 3; pass++){
            const uint32_t aOff = aBase + ((pass == 1) ? ARR_BYTES : 0);
            const uint32_t bOff = bBase + ((pass == 2) ? ARR_BYTES : 0);
            #pragma unroll
            for (int ks = 0; ks < 2; ks++){
                const uint32_t kb = ks*32;
                uint32_t aq[4][4], bq[2][4];
                #pragma unroll
                for (int mt = 0; mt < 4; mt++)
                    ldsm4(aq[mt], aOff + mt*16*80 + kb);
                ldsm4(bq[0], bOff + kb);
                ldsm4(bq[1], bOff + 16*80 + kb);
                #pragma unroll
                for (int mt = 0; mt < 4; mt++)
                    #pragma unroll
                    for (int nt = 0; nt < 4; nt++)
                        mma16816(acc[mt][nt], aq[mt],
                                 bq[nt>>1][nt&1], bq[nt>>1][2+(nt&1)]);
            }
        }
        __syncthreads();
        if (c + 2 < 16){
            uint32_t dst = sb + (c & 1)*STAGE_BYTES;
            loadB_async(Bhi, Blo, n0, (c+2)*32, dst, tid);
            asm volatile("cp.async.commit_group;" ::: "memory");
            stsA(dst, tid, pa);
            if (c + 3 < 16) prefetchA(A, m0, (c+3)*32, tid, pa);
        }
    }

    #pragma unroll
    for (int mt = 0; mt < 4; mt++){
        #pragma unroll
        for (int nt = 0; nt < 4; nt++){
            int r   = m0 + wm64 + mt*16 + grp;
            int col = n0 + wn32 + nt*8 + q2;
            float b0 = bias[col], b1 = bias[col+1];
            float2 v0 = make_float2(acc[mt][nt][0] + b0, acc[mt][nt][1] + b1);
            float2 v1 = make_float2(acc[mt][nt][2] + b0, acc[mt][nt][3] + b1);
            *(float2*)(C + (size_t)r*512 + col)     = v0;
            *(float2*)(C + (size_t)(r+8)*512 + col) = v1;
        }
    }
}

__global__ __launch_bounds__(256,2) void gemm_mma(
    const float* __restrict__ A,
    const __nv_bfloat16* __restrict__ Bhi, const __nv_bfloat16* __restrict__ Blo,
    const float* __restrict__ bias, float* __restrict__ C)
{
    extern __shared__ char smem[];
    gemm_body(A, Bhi, Blo, bias, C, smem);
}

// dual GEMM: z selects (q, k) projections — one launch, better wave packing
__global__ __launch_bounds__(256,2) void gemm_mma2(
    const float* __restrict__ A0, const float* __restrict__ A1,
    const __nv_bfloat16* __restrict__ B0h, const __nv_bfloat16* __restrict__ B0l,
    const __nv_bfloat16* __restrict__ B1h, const __nv_bfloat16* __restrict__ B1l,
    const float* __restrict__ bias0, const float* __restrict__ bias1,
    float* __restrict__ C0, float* __restrict__ C1)
{
    extern __shared__ char smem[];
    if (blockIdx.z == 0) gemm_body(A0, B0h, B0l, bias0, C0, smem);
    else                 gemm_body(A1, B1h, B1l, bias1, C1, smem);
}

// ---------------- fused wavelet (q and k in one launch, grid.z = 2) ----------------
__global__ __launch_bounds__(256) void wavelet_qk(
    const float* __restrict__ qx, float* __restrict__ qd, float* __restrict__ qs,
    const float* __restrict__ kx, float* __restrict__ kd, float* __restrict__ ks,
    const float* __restrict__ ecd, const float* __restrict__ ecs,
    int Lh, int total)
{
    __shared__ float wd[16][8], ws[16][8];
    int tid = threadIdx.x;
    if (tid < 128){ ((float*)wd)[tid] = ecd[tid]; ((float*)ws)[tid] = ecs[tid]; }
    __syncthreads();
    int idx = blockIdx.x*256 + tid;
    if (idx >= total) return;
    const float* x = blockIdx.z ? kx : qx;
    float* d = blockIdx.z ? kd : qd;
    float* s = blockIdx.z ? ks : qs;
    int c = idx & 63;
    int j = (idx >> 6) % Lh;
    int b = idx / (Lh << 6);
    const float* xe = x + (((size_t)b*(Lh<<1) + 2*j)*64 + c)*8;
    float xa[16];
    *(float4*)(xa)    = *(const float4*)(xe);
    *(float4*)(xa+4)  = *(const float4*)(xe+4);
    *(float4*)(xa+8)  = *(const float4*)(xe+512);
    *(float4*)(xa+12) = *(const float4*)(xe+516);
    float dv[8], sv[8];
    #pragma unroll
    for (int k2=0;k2<8;k2++){ dv[k2]=0.f; sv[k2]=0.f; }
    #pragma unroll
    for (int t=0;t<16;t++){
        float xv = xa[t];
        #pragma unroll
        for (int k2=0;k2<8;k2++){ dv[k2] += xv*wd[t][k2]; sv[k2] += xv*ws[t][k2]; }
    }
    float* dp = d + (size_t)idx*8;
    float* sp = s + (size_t)idx*8;
    *(float4*)(dp)   = make_float4(dv[0],dv[1],dv[2],dv[3]);
    *(float4*)(dp+4) = make_float4(dv[4],dv[5],dv[6],dv[7]);
    *(float4*)(sp)   = make_float4(sv[0],sv[1],sv[2],sv[3]);
    *(float4*)(sp+4) = make_float4(sv[4],sv[5],sv[6],sv[7]);
}

// ---------------- forward DFT ----------------
__global__ __launch_bounds__(256) void dft_kernel(
    const float* __restrict__ t0, const float* __restrict__ t1,
    const float* __restrict__ t2, const float* __restrict__ t3,
    float* __restrict__ S, int Lh, int m)
{
    __shared__ float2 tw2[512];
    __shared__ float pr[16][128], pi[16][128];
    const int tid = threadIdx.x;
    const int b = blockIdx.x, tensor = blockIdx.y, ck0 = blockIdx.z * 128;
    for (int r = tid; r < Lh; r += 256){
        float sv, cv;
        sincosf(6.283185307179586f * ((float)r / (float)Lh), &sv, &cv);
        tw2[r] = make_float2(cv, sv);
    }
    __syncthreads();
    const float* X = (tensor==0) ? t0 : (tensor==1) ? t1 : (tensor==2) ? t2 : t3;
    const int col  = tid & 127;
    const int half = tid >> 7;
    const int Lh2  = Lh >> 1;
    const float* p = X + ((size_t)b*Lh + (size_t)half*Lh2)*512 + ck0 + col;
    float ar[16], ai[16];
    #pragma unroll
    for (int f=0; f<16; f++){ ar[f]=0.f; ai[f]=0.f; }
    for (int li=0; li<Lh2; li++){
        const int l = half*Lh2 + li;
        float xv = p[(size_t)li*512];
        int r = 0;
        #pragma unroll
        for (int f=0; f<16; f++){
            float2 t = tw2[r];
            ar[f] += xv * t.x;
            ai[f] += xv * t.y;
            r += l; if (r >= Lh) r -= Lh;
        }
    }
    if (half){
        #pragma unroll
        for (int f=0; f<16; f++){ pr[f][col]=ar[f]; pi[f][col]=ai[f]; }
    }
    __syncthreads();
    if (!half){
        float* out = S + (((size_t)b*4 + tensor)*2*16)*512 + ck0 + col;
        for (int f=0; f<m; f++){
            out[(size_t)f*512]        =  ar[f] + pr[f][col];
            out[8192 + (size_t)f*512] = -(ai[f] + pi[f][col]);
        }
    }
}

// ---------------- mid (shallow levels) ----------------
__global__ __launch_bounds__(256) void mid_kernel(const float* __restrict__ S,
    float* __restrict__ O, int m)
{
    __shared__ float Sqr[64][16], Sqi[64][16], Skr[64][16], Ski[64][16];
    __shared__ float QKr[16][17], QKi[16][17];
    const int tid = threadIdx.x;
    const int b = blockIdx.x >> 3, h = blockIdx.x & 7;
    const int which = blockIdx.y;

    const float* base = S + (size_t)(b*4 + which*2)*2*16*512;
    for (int idx = tid; idx < 64*16; idx += 256){
        int e = idx >> 4, f = idx & 15;
        size_t o = (size_t)f*512 + e*8 + h;
        Sqr[e][f] = base[o];
        Sqi[e][f] = base[o + 8192];
        Skr[e][f] = base[o + 16384];
        Ski[e][f] = base[o + 24576];
    }
    __syncthreads();

    if (tid < m*m){
        int x = tid / m, y = tid - (tid/m)*m;
        float sr=0.f, sim=0.f;
        #pragma unroll 8
        for (int e=0;e<64;e++){
            float qr=Sqr[e][x], qi=Sqi[e][x];
            float kr=Skr[e][y], ki=Ski[e][y];
            sr  += qr*kr - qi*ki;
            sim += qr*ki + qi*kr;
        }
        float txx = tanhf(sr);
        float tyy = tanf(sim);
        float tx2=txx*txx, ty2=tyy*tyy;
        float den = 1.0f + tx2*ty2;
        QKr[x][y] = txx*(1.0f+ty2)/den;
        QKi[x][y] = tyy*(1.0f-tx2)/den;
    }
    __syncthreads();

    float* ob = O + (size_t)(b*2 + which)*2*16*512;
    for (int t = tid; t < 64*m; t += 256){
        int x = t % m, e = t / m;
        float orr=0.f, oii=0.f;
        for (int y=0;y<m;y++){
            float ar=QKr[x][y], ai2=QKi[x][y];
            float br=Skr[e][y], bi=Ski[e][y];
            orr += ar*br - ai2*bi;
            oii += ar*bi + ai2*br;
        }
        size_t o = (size_t)x*512 + e*8 + h;
        ob[o]        = orr;
        ob[o + 8192] = oii;
    }
}

// ---------------- inverse DFT + fused add (shallow levels) ----------------
__global__ __launch_bounds__(256) void idft_kernel(const float* __restrict__ O,
    float* __restrict__ Us, float* __restrict__ Ud,
    int Lh, int m, float scale, int rows)
{
    __shared__ float twc[512], tws[512];
    __shared__ float Osm[2][2][16][128];
    const int tid = threadIdx.x;
    const int b = blockIdx.x, ck0 = blockIdx.y * 128;
    for (int r = tid; r < Lh; r += 256){
        float sv, cv;
        sincosf(6.283185307179586f * ((float)r / (float)Lh), &sv, &cv);
        twc[r]=cv; tws[r]=sv;
    }
    for (int idx = tid; idx < 2*2*16*128; idx += 256){
        int w    = idx >> 12;
        int rem  = idx & 4095;
        int reim = rem >> 11;
        int f    = (rem >> 7) & 15;
        int col  = rem & 127;
        Osm[w][reim][f][col] =
            O[(size_t)((b*2 + w)*2 + reim)*8192 + (size_t)f*512 + ck0 + col];
    }
    __syncthreads();
    const int l0 = blockIdx.z * rows;
    for (int t = tid; t < rows*128; t += 256){
        int lr = t >> 7, col = t & 127;
        int l = l0 + lr;
        float as = Osm[0][0][0][col];
        float ad = Osm[1][0][0][col];
        int r = 0;
        for (int f=1; f<m; f++){
            r += l; if (r >= Lh) r -= Lh;
            float c = twc[r], s = tws[r];
            as += 2.0f*(Osm[0][0][f][col]*c - Osm[0][1][f][col]*s);
            ad += 2.0f*(Osm[1][0][f][col]*c - Osm[1][1][f][col]*s);
        }
        size_t oi = ((size_t)b*Lh + l)*512 + ck0 + col;
        float usv = as * scale;
        Us[oi] = usv;
        Ud[oi] = ad * scale + usv;
    }
}

// ---------------- midft_deep: mid + idft fused, levels with Lh<=64 ----------------
// grid: 128 blocks = (16 b x 8 h), 256 threads. O spectra stay in smem.
__global__ __launch_bounds__(256) void midft_deep(
    const float* __restrict__ S, float* __restrict__ Us, float* __restrict__ Ud,
    int Lh, int m, float scale)
{
    __shared__ float2 tw2[64];
    __shared__ float sq[2][64][16], sk[2][64][16];      // [reim][e][f] (one which at a time)
    __shared__ float Or_[2][64][16], Oi_[2][64][16];    // [which][e][f]
    __shared__ float qkr[16][17], qki[16][17];
    const int b = blockIdx.x >> 3, h = blockIdx.x & 7;
    const int tid = threadIdx.x;

    if (tid < Lh){
        float sv, cv;
        sincosf(6.283185307179586f*((float)tid/(float)Lh), &sv, &cv);
        tw2[tid] = make_float2(cv, sv);
    }

    for (int which = 0; which < 2; which++){
        // load spectra of this which (qk tensors which*2, which*2+1)
        for (int it = tid; it < 4096; it += 256){
            int qk = it >> 11;                // 0=q, 1=k
            int ri = (it >> 10) & 1;
            int e  = (it >> 4) & 63;
            int f  = it & 15;
            int tensor = which*2 + qk;
            float v = (f < m)
                ? S[((size_t)(b*4 + tensor)*2 + ri)*8192 + (size_t)f*512 + e*8 + h]
                : 0.f;
            if (qk == 0) sq[ri][e][f] = v; else sk[ri][e][f] = v;
        }
        __syncthreads();
        if (tid < m*m){
            int x = tid / m, y = tid - (tid/m)*m;
            float sr=0.f, sim=0.f;
            #pragma unroll 8
            for (int e=0;e<64;e++){
                float qr=sq[0][e][x], qi=sq[1][e][x];
                float kr=sk[0][e][y], ki=sk[1][e][y];
                sr  += qr*kr - qi*ki;
                sim += qr*ki + qi*kr;
            }
            float txx = tanhf(sr);
            float tyy = tanf(sim);
            float tx2=txx*txx, ty2=tyy*tyy;
            float den = 1.0f + tx2*ty2;
            qkr[x][y] = txx*(1.0f+ty2)/den;
            qki[x][y] = tyy*(1.0f-tx2)/den;
        }
        __syncthreads();
        for (int t = tid; t < 64*m; t += 256){
            int x = t % m, e = t / m;
            float orr=0.f, oii=0.f;
            for (int y=0;y<m;y++){
                float ar=qkr[x][y], ai2=qki[x][y];
                float br=sk[0][e][y], bi=sk[1][e][y];
                orr += ar*br - ai2*bi;
                oii += ar*bi + ai2*br;
            }
            Or_[which][e][x] = orr;
            Oi_[which][e][x] = oii;
        }
        __syncthreads();   // Or_ done; also releases sq/sk/qkr for next which
    }

    // inverse DFT: Lh*64 outputs for this (b,h)
    for (int t = tid; t < Lh*64; t += 256){
        int l = t >> 6, e = t & 63;
        float as = Or_[0][e][0];
        float ad = Or_[1][e][0];
        int r = 0;
        for (int f=1; f<m; f++){
            r += l; if (r >= Lh) r -= Lh;
            float c = tw2[r].x, s = tw2[r].y;
            as += 2.f*(Or_[0][e][f]*c - Oi_[0][e][f]*s);
            ad += 2.f*(Or_[1][e][f]*c - Oi_[1][e][f]*s);
        }
        size_t oi = ((size_t)b*Lh + l)*512 + e*8 + h;
        float usv = as*scale;
        Us[oi] = usv;
        Ud[oi] = ad*scale + usv;
    }
}

// ---------------- DEEP recon: lev 9..4 (Lv 1 -> 64), one block per b (R12-proven) ----------------
#define DSCR 262144
__global__ __launch_bounds__(512) void deep_recon(
    const float* __restrict__ us, const float* __restrict__ ud,
    const float* __restrict__ rce, const float* __restrict__ rco,
    float* __restrict__ vscr, float* __restrict__ vout)
{
    const int b = blockIdx.x, tid = threadIdx.x;
    __shared__ float we[16][8], wo[16][8];
    if (tid < 128){ ((float*)we)[tid] = rce[tid]; ((float*)wo)[tid] = rco[tid]; }
    float* vA = vscr + (size_t)b*DSCR;
    float* vc = vA; float* vn = vA + 32768;
    if (tid < 512) vc[tid] = 0.f;
    __syncthreads();
    int Lv = 1;
    for (int lev = 9; lev >= 4; lev--){
        size_t o = doffs(lev) + (size_t)b*Lv*512;
        int items = Lv*64;
        for (int it = tid; it < items; it += 512){
            int c = it & 63, l = it >> 6;
            const float* vp = vc + (size_t)it*8;
            const float* up = us + o + (size_t)it*8;
            const float* dp = ud + o + (size_t)it*8;
            float w[16];
            #pragma unroll
            for (int t=0;t<8;t++) w[t]   = vp[t] + up[t];
            #pragma unroll
            for (int t=0;t<8;t++) w[8+t] = dp[t];
            float ev[8], ov[8];
            #pragma unroll
            for (int k2=0;k2<8;k2++){ ev[k2]=0.f; ov[k2]=0.f; }
            #pragma unroll
            for (int t=0;t<16;t++){
                float xv = w[t];
                #pragma unroll
                for (int k2=0;k2<8;k2++){ ev[k2] += xv*we[t][k2]; ov[k2] += xv*wo[t][k2]; }
            }
            float* op = vn + (size_t)(2*l)*512 + c*8;
            *(float4*)(op)     = make_float4(ev[0],ev[1],ev[2],ev[3]);
            *(float4*)(op+4)   = make_float4(ev[4],ev[5],ev[6],ev[7]);
            *(float4*)(op+512) = make_float4(ov[0],ov[1],ov[2],ov[3]);
            *(float4*)(op+516) = make_float4(ov[4],ov[5],ov[6],ov[7]);
        }
        __syncthreads();
        float* t = vc; vc = vn; vn = t;
        Lv <<= 1;
    }
    for (int it = tid; it < 32768; it += 512)
        vout[(size_t)b*32768 + it] = vc[it];
}

// ---------------- recon (shallow) ----------------
__global__ __launch_bounds__(256) void recon_kernel(const float* __restrict__ v,
    const float* __restrict__ Us, const float* __restrict__ Ud,
    const float* __restrict__ rce, const float* __restrict__ rco,
    float* __restrict__ outv, int Lv, int total)
{
    __shared__ float we[16][8], wo[16][8];
    int tid = threadIdx.x;
    if (tid < 128){ ((float*)we)[tid] = rce[tid]; ((float*)wo)[tid] = rco[tid]; }
    __syncthreads();
    int idx = blockIdx.x*256 + tid;
    if (idx >= total) return;
    int c = idx & 63;
    int l = (idx >> 6) % Lv;
    int b = idx / (Lv << 6);
    const float* vp = v  + (size_t)idx*8;
    const float* up = Us + (size_t)idx*8;
    const float* dp = Ud + (size_t)idx*8;
    float w[16];
    #pragma unroll
    for (int t=0;t<8;t++) w[t]   = vp[t] + up[t];
    #pragma unroll
    for (int t=0;t<8;t++) w[8+t] = dp[t];
    float ev[8], ov[8];
    #pragma unroll
    for (int k2=0;k2<8;k2++){ ev[k2]=0.f; ov[k2]=0.f; }
    #pragma unroll
    for (int t=0;t<16;t++){
        float xv = w[t];
        #pragma unroll
        for (int k2=0;k2<8;k2++){ ev[k2] += xv*we[t][k2]; ov[k2] += xv*wo[t][k2]; }
    }
    float* op = outv + (((size_t)b*(Lv<<1) + 2*l)*64 + c)*8;
    *(float4*)(op)     = make_float4(ev[0],ev[1],ev[2],ev[3]);
    *(float4*)(op+4)   = make_float4(ev[4],ev[5],ev[6],ev[7]);
    *(float4*)(op+512) = make_float4(ov[0],ov[1],ov[2],ov[3]);
    *(float4*)(op+516) = make_float4(ov[4],ov[5],ov[6],ov[7]);
}

// ---------------- orchestration ----------------
extern "C" void kernel_launch(void* const* d_in, const int* in_sizes, int n_in,
                              void* d_out, int out_size)
{
    (void)in_sizes; (void)n_in; (void)out_size;
    const float* q     = (const float*)d_in[0];
    const float* k     = (const float*)d_in[1];
    const float* Lq_w  = (const float*)d_in[3];
    const float* Lq_b  = (const float*)d_in[4];
    const float* Lk_w  = (const float*)d_in[5];
    const float* Lk_b  = (const float*)d_in[6];
    const float* out_w = (const float*)d_in[9];
    const float* out_b = (const float*)d_in[10];
    const float* ec_s  = (const float*)d_in[11];
    const float* ec_d  = (const float*)d_in[12];
    const float* rc_e  = (const float*)d_in[13];
    const float* rc_o  = (const float*)d_in[14];
    float* outp = (float*)d_out;

    float *bufA,*bufB,*kA,*kB,*dq,*dk,*us,*ud,*S,*O;
    __nv_bfloat16 *Wthi,*Wtlo,*W2hi,*W2lo,*W3hi,*W3lo;
    cudaGetSymbolAddress((void**)&bufA, g_bufA);
    cudaGetSymbolAddress((void**)&bufB, g_bufB);
    cudaGetSymbolAddress((void**)&kA,   g_kA);
    cudaGetSymbolAddress((void**)&kB,   g_kB);
    cudaGetSymbolAddress((void**)&dq,   g_dq);
    cudaGetSymbolAddress((void**)&dk,   g_dk);
    cudaGetSymbolAddress((void**)&us,   g_Us);
    cudaGetSymbolAddress((void**)&ud,   g_Ud);
    cudaGetSymbolAddress((void**)&S,    g_S);
    cudaGetSymbolAddress((void**)&O,    g_O);
    cudaGetSymbolAddress((void**)&Wthi, g_Wthi);
    cudaGetSymbolAddress((void**)&Wtlo, g_Wtlo);
    cudaGetSymbolAddress((void**)&W2hi, g_W2hi);
    cudaGetSymbolAddress((void**)&W2lo, g_W2lo);
    cudaGetSymbolAddress((void**)&W3hi, g_W3hi);
    cudaGetSymbolAddress((void**)&W3lo, g_W3lo);

    cudaFuncSetAttribute(gemm_mma,  cudaFuncAttributeMaxDynamicSharedMemorySize, GEMM_SMEM);
    cudaFuncSetAttribute(gemm_mma2, cudaFuncAttributeMaxDynamicSharedMemorySize, GEMM_SMEM);

    size_t offs[10]; size_t off=0;
    { int L = 1024;
      for (int i=0;i<10;i++){ int Lh = L >> 1; offs[i] = off; off += (size_t)16*Lh*512; L = Lh; } }

    convW3_kernel<<<dim3(16,16,3),256>>>(Lq_w, Lk_w, out_w,
                                         Wthi, Wtlo, W2hi, W2lo, W3hi, W3lo);
    zero2_kernel<<<32,256>>>(us+offs[9], ud+offs[9], 16*1*512);
    gemm_mma2<<<dim3(4,128,2),256,GEMM_SMEM>>>(q, k, Wthi, Wtlo, W2hi, W2lo,
                                               Lq_b, Lk_b, bufA, kA);

    float *qc=bufA,*qn=bufB,*kc=kA,*kn=kB;
    int L = 1024;
    for (int i=0;i<9;i++){
        int Lh = L >> 1;
        int m  = (Lh>>1) < 16 ? (Lh>>1) : 16;
        int total = 16*Lh*64;
        int blocks = (total + 255)/256;
        wavelet_qk<<<dim3(blocks,1,2),256>>>(qc, dq, qn, kc, dk, kn, ec_d, ec_s, Lh, total);
        dft_kernel<<<dim3(16,4,4),256>>>(dq, dk, qn, kn, S, Lh, m);
        float inv_scale = 1.0f/(4096.0f*(float)Lh);
        if (Lh > 64){
            mid_kernel<<<dim3(128,2),256>>>(S, O, m);
            int lsplit = Lh/64;
            idft_kernel<<<dim3(16,4,lsplit),256>>>(O, us+offs[i], ud+offs[i], Lh, m, inv_scale, 64);
        } else {
            midft_deep<<<128,256>>>(S, us+offs[i], ud+offs[i], Lh, m, inv_scale);
        }
        float* t; t=qc; qc=qn; qn=t;  t=kc; kc=kn; kn=t;
        L = Lh;
    }

    // deep recon (Lv 1 -> 64) -> bufA packed b*64*512  (dq is dead scratch here)
    deep_recon<<<16,512>>>(us, ud, rc_e, rc_o, dq, bufA);

    // shallow recon i = 3..0
    float *vc=bufA, *vn=bufB;
    int Lv = 64;
    for (int i=3;i>=0;i--){
        int total = 16*Lv*64;
        recon_kernel<<<(total+255)/256,256>>>(vc, us+offs[i], ud+offs[i],
                                              rc_e, rc_o, vn, Lv, total);
        float* t=vc; vc=vn; vn=t;
        Lv <<= 1;
    }
    // 4 swaps -> final v in bufA (vc)

    gemm_mma<<<dim3(4,128),256,GEMM_SMEM>>>(vc, W3hi, W3lo, out_b, outp);
}

// round 16
// speedup vs baseline: 1.6468x; 1.0951x over previous
#include <cuda_runtime.h>
#include <cuda_bf16.h>
#include <math.h>
#include <stdint.h>

// Problem constants
#define NB   16
#define NSEQ 1024
#define CK   512          // C*K

// -------- scratch (device globals; no allocation allowed) --------
__device__ float g_bufA[NB*NSEQ*CK];
__device__ float g_bufB[NB*NSEQ*CK];
__device__ float g_kA[NB*NSEQ*CK];
__device__ float g_kB[NB*NSEQ*CK];
__device__ float g_dq[NB*512*CK];
__device__ float g_dk[NB*512*CK];
__device__ float g_Us[NB*1023*CK];
__device__ float g_Ud[NB*1023*CK];
__device__ float g_S[NB*4*2*16*CK];   // spectra
__device__ float g_O[NB*2*2*16*CK];   // post-attn spectra
__device__ __nv_bfloat16 g_Wthi[CK*CK];
__device__ __nv_bfloat16 g_Wtlo[CK*CK];
__device__ __nv_bfloat16 g_W2hi[CK*CK];
__device__ __nv_bfloat16 g_W2lo[CK*CK];
__device__ __nv_bfloat16 g_W3hi[CK*CK];
__device__ __nv_bfloat16 g_W3lo[CK*CK];

__device__ __forceinline__ uint32_t smem_u32(const void* p){
    uint32_t a;
    asm("{ .reg .u64 t; cvta.to.shared.u64 t, %1; cvt.u32.u64 %0, t; }" : "=r"(a) : "l"(p));
    return a;
}

// ---- convW3: three W fp32 [K,N] -> transposed bf16 hi/lo pairs (one launch) ----
__global__ __launch_bounds__(256) void convW3_kernel(
    const float* __restrict__ W0, const float* __restrict__ W1, const float* __restrict__ W2,
    __nv_bfloat16* h0, __nv_bfloat16* l0,
    __nv_bfloat16* h1, __nv_bfloat16* l1,
    __nv_bfloat16* h2, __nv_bfloat16* l2)
{
    __shared__ float t[32][33];
    int z = blockIdx.z;
    const float* W = (z==0) ? W0 : (z==1) ? W1 : W2;
    __nv_bfloat16* hi = (z==0) ? h0 : (z==1) ? h1 : h2;
    __nv_bfloat16* lo = (z==0) ? l0 : (z==1) ? l1 : l2;
    int bx = blockIdx.x, by = blockIdx.y;
    int tx = threadIdx.x & 31, ty = threadIdx.x >> 5;
    for (int i = ty; i < 32; i += 8)
        t[i][tx] = W[(size_t)(bx*32 + i)*512 + by*32 + tx];
    __syncthreads();
    for (int i = ty; i < 32; i += 8){
        float v = t[tx][i];
        __nv_bfloat16 h = __float2bfloat16(v);
        size_t o = (size_t)(by*32 + i)*512 + bx*32 + tx;
        hi[o] = h;
        lo[o] = __float2bfloat16(v - __bfloat162float(h));
    }
}

__global__ void zero2_kernel(float* p1, float* p2, int n){
    int i = blockIdx.x*blockDim.x + threadIdx.x;
    if (i < n){ p1[i] = 0.f; p2[i] = 0.f; }
}

__global__ void zero_kernel(float* p, int n){
    int i = blockIdx.x*blockDim.x + threadIdx.x;
    if (i < n) p[i] = 0.f;
}

// ================= tensor-core GEMM (R11-proven mainloop) =================
#define STAGE_BYTES 40960
#define ARR_BYTES   10240
#define GEMM_SMEM   (2*STAGE_BYTES)

__device__ __forceinline__ void mma16816(float* d, const uint32_t* a, uint32_t b0, uint32_t b1){
    asm volatile(
        "mma.sync.aligned.m16n8k16.row.col.f32.bf16.bf16.f32 "
        "{%0,%1,%2,%3}, {%4,%5,%6,%7}, {%8,%9}, {%0,%1,%2,%3};"
        : "+f"(d[0]), "+f"(d[1]), "+f"(d[2]), "+f"(d[3])
        : "r"(a[0]), "r"(a[1]), "r"(a[2]), "r"(a[3]), "r"(b0), "r"(b1));
}
__device__ __forceinline__ void ldsm4(uint32_t* r, uint32_t addr){
    asm volatile("ldmatrix.sync.aligned.m8n8.x4.shared.b16 {%0,%1,%2,%3}, [%4];"
        : "=r"(r[0]), "=r"(r[1]), "=r"(r[2]), "=r"(r[3]) : "r"(addr));
}
__device__ __forceinline__ void loadB_async(
    const __nv_bfloat16* __restrict__ Bhi, const __nv_bfloat16* __restrict__ Blo,
    int n0, int k0, uint32_t sstage, int tid)
{
    #pragma unroll
    for (int t = 4; t < 8; t++){
        const int arr = t >> 1;
        const int row = (t & 1)*64 + (tid >> 2);
        const int seg = tid & 3;
        const __nv_bfloat16* g = ((arr == 2) ? Bhi : Blo) + (size_t)(n0 + row)*512 + k0 + seg*8;
        uint32_t d = sstage + arr*ARR_BYTES + row*80 + seg*16;
        asm volatile("cp.async.cg.shared.global [%0], [%1], 16;" :: "r"(d), "l"(g));
    }
}
__device__ __forceinline__ void prefetchA(const float* __restrict__ A,
    int m0, int k0, int tid, float4* pa)
{
    #pragma unroll
    for (int t = 0; t < 2; t++){
        int idx = tid + t*256;
        int row = idx >> 2, seg = idx & 3;
        const float* g = A + (size_t)(m0 + row)*512 + k0 + seg*8;
        pa[2*t]   = *(const float4*)g;
        pa[2*t+1] = *(const float4*)(g + 4);
    }
}
__device__ __forceinline__ uint32_t pack2(__nv_bfloat16 a, __nv_bfloat16 b){
    __nv_bfloat162 h; h.x = a; h.y = b;
    return *(uint32_t*)&h;
}
__device__ __forceinline__ void stsA(uint32_t sstage, int tid, const float4* pa){
    #pragma unroll
    for (int t = 0; t < 2; t++){
        int idx = tid + t*256;
        int row = idx >> 2, seg = idx & 3;
        float4 v0 = pa[2*t], v1 = pa[2*t+1];
        __nv_bfloat16 h0 = __float2bfloat16(v0.x), h1 = __float2bfloat16(v0.y);
        __nv_bfloat16 h2 = __float2bfloat16(v0.z), h3 = __float2bfloat16(v0.w);
        __nv_bfloat16 h4 = __float2bfloat16(v1.x), h5 = __float2bfloat16(v1.y);
        __nv_bfloat16 h6 = __float2bfloat16(v1.z), h7 = __float2bfloat16(v1.w);
        uint4 hv;
        hv.x = pack2(h0, h1); hv.y = pack2(h2, h3);
        hv.z = pack2(h4, h5); hv.w = pack2(h6, h7);
        uint4 lv;
        lv.x = pack2(__float2bfloat16(v0.x - __bfloat162float(h0)),
                     __float2bfloat16(v0.y - __bfloat162float(h1)));
        lv.y = pack2(__float2bfloat16(v0.z - __bfloat162float(h2)),
                     __float2bfloat16(v0.w - __bfloat162float(h3)));
        lv.z = pack2(__float2bfloat16(v1.x - __bfloat162float(h4)),
                     __float2bfloat16(v1.y - __bfloat162float(h5)));
        lv.w = pack2(__float2bfloat16(v1.z - __bfloat162float(h6)),
                     __float2bfloat16(v1.w - __bfloat162float(h7)));
        uint32_t dhi = sstage + row*80 + seg*16;
        asm volatile("st.shared.v4.b32 [%0], {%1,%2,%3,%4};"
                     :: "r"(dhi), "r"(hv.x), "r"(hv.y), "r"(hv.z), "r"(hv.w) : "memory");
        asm volatile("st.shared.v4.b32 [%0], {%1,%2,%3,%4};"
                     :: "r"(dhi + ARR_BYTES), "r"(lv.x), "r"(lv.y), "r"(lv.z), "r"(lv.w) : "memory");
    }
}

__device__ __forceinline__ void gemm_body(
    const float* __restrict__ A,
    const __nv_bfloat16* __restrict__ Bhi, const __nv_bfloat16* __restrict__ Blo,
    const float* __restrict__ bias, float* __restrict__ C, char* smem)
{
    uint32_t sb = smem_u32(smem);
    const int tid  = threadIdx.x;
    const int lane = tid & 31, warp = tid >> 5;
    const int wm64 = (warp >> 2) * 64, wn32 = (warp & 3) * 32;
    const int grp  = lane >> 2,  q2   = (lane & 3) * 2;
    const int n0 = blockIdx.x * 128, m0 = blockIdx.y * 128;
    const int lrow = (lane & 7) + ((lane >> 3) & 1) * 8;
    const int lcol = (lane >> 4) * 8;

    float acc[4][4][4];
    #pragma unroll
    for (int i=0;i<4;i++)
        #pragma unroll
        for (int j=0;j<4;j++)
            #pragma unroll
            for (int r=0;r<4;r++) acc[i][j][r]=0.f;

    float4 pa[4];
    prefetchA(A, m0, 0, tid, pa);
    loadB_async(Bhi, Blo, n0, 0, sb, tid);
    asm volatile("cp.async.commit_group;" ::: "memory");
    stsA(sb, tid, pa);
    prefetchA(A, m0, 32, tid, pa);
    loadB_async(Bhi, Blo, n0, 32, sb + STAGE_BYTES, tid);
    asm volatile("cp.async.commit_group;" ::: "memory");
    stsA(sb + STAGE_BYTES, tid, pa);
    prefetchA(A, m0, 64, tid, pa);

    for (int c = 0; c < 16; c++){
        if (c < 15) asm volatile("cp.async.wait_group 1;" ::: "memory");
        else        asm volatile("cp.async.wait_group 0;" ::: "memory");
        __syncthreads();

        const uint32_t st = sb + (c & 1)*STAGE_BYTES;
        const uint32_t aBase = st + (wm64 + lrow)*80 + lcol*2;
        const uint32_t bBase = st + 2*ARR_BYTES + (wn32 + lrow)*80 + lcol*2;

        #pragma unroll
        for (int pass = 0; pass < 3; pass++){
            const uint32_t aOff = aBase + ((pass == 1) ? ARR_BYTES : 0);
            const uint32_t bOff = bBase + ((pass == 2) ? ARR_BYTES : 0);
            #pragma unroll
            for (int ks = 0; ks < 2; ks++){
                const uint32_t kb = ks*32;
                uint32_t aq[4][4], bq[2][4];
                #pragma unroll
                for (int mt = 0; mt < 4; mt++)
                    ldsm4(aq[mt], aOff + mt*16*80 + kb);
                ldsm4(bq[0], bOff + kb);
                ldsm4(bq[1], bOff + 16*80 + kb);
                #pragma unroll
                for (int mt = 0; mt < 4; mt++)
                    #pragma unroll
                    for (int nt = 0; nt < 4; nt++)
                        mma16816(acc[mt][nt], aq[mt],
                                 bq[nt>>1][nt&1], bq[nt>>1][2+(nt&1)]);
            }
        }
        __syncthreads();
        if (c + 2 < 16){
            uint32_t dst = sb + (c & 1)*STAGE_BYTES;
            loadB_async(Bhi, Blo, n0, (c+2)*32, dst, tid);
            asm volatile("cp.async.commit_group;" ::: "memory");
            stsA(dst, tid, pa);
            if (c + 3 < 16) prefetchA(A, m0, (c+3)*32, tid, pa);
        }
    }

    #pragma unroll
    for (int mt = 0; mt < 4; mt++){
        #pragma unroll
        for (int nt = 0; nt < 4; nt++){
            int r   = m0 + wm64 + mt*16 + grp;
            int col = n0 + wn32 + nt*8 + q2;
            float b0 = bias[col], b1 = bias[col+1];
            float2 v0 = make_float2(acc[mt][nt][0] + b0, acc[mt][nt][1] + b1);
            float2 v1 = make_float2(acc[mt][nt][2] + b0, acc[mt][nt][3] + b1);
            *(float2*)(C + (size_t)r*512 + col)     = v0;
            *(float2*)(C + (size_t)(r+8)*512 + col) = v1;
        }
    }
}

__global__ __launch_bounds__(256,2) void gemm_mma(
    const float* __restrict__ A,
    const __nv_bfloat16* __restrict__ Bhi, const __nv_bfloat16* __restrict__ Blo,
    const float* __restrict__ bias, float* __restrict__ C)
{
    extern __shared__ char smem[];
    gemm_body(A, Bhi, Blo, bias, C, smem);
}

// dual GEMM: z selects (q, k) projections — one launch, same wave structure
__global__ __launch_bounds__(256,2) void gemm_mma2(
    const float* __restrict__ A0, const float* __restrict__ A1,
    const __nv_bfloat16* __restrict__ B0h, const __nv_bfloat16* __restrict__ B0l,
    const __nv_bfloat16* __restrict__ B1h, const __nv_bfloat16* __restrict__ B1l,
    const float* __restrict__ bias0, const float* __restrict__ bias1,
    float* __restrict__ C0, float* __restrict__ C1)
{
    extern __shared__ char smem[];
    if (blockIdx.z == 0) gemm_body(A0, B0h, B0l, bias0, C0, smem);
    else                 gemm_body(A1, B1h, B1l, bias1, C1, smem);
}

// ---------------- fused wavelet (q and k in one launch, grid.z = 2) ----------------
__global__ __launch_bounds__(256) void wavelet_qk(
    const float* __restrict__ qx, float* __restrict__ qd, float* __restrict__ qs,
    const float* __restrict__ kx, float* __restrict__ kd, float* __restrict__ ks,
    const float* __restrict__ ecd, const float* __restrict__ ecs,
    int Lh, int total)
{
    __shared__ float wd[16][8], ws[16][8];
    int tid = threadIdx.x;
    if (tid < 128){ ((float*)wd)[tid] = ecd[tid]; ((float*)ws)[tid] = ecs[tid]; }
    __syncthreads();
    int idx = blockIdx.x*256 + tid;
    if (idx >= total) return;
    const float* x = blockIdx.z ? kx : qx;
    float* d = blockIdx.z ? kd : qd;
    float* s = blockIdx.z ? ks : qs;
    int c = idx & 63;
    int j = (idx >> 6) % Lh;
    int b = idx / (Lh << 6);
    const float* xe = x + (((size_t)b*(Lh<<1) + 2*j)*64 + c)*8;
    float xa[16];
    *(float4*)(xa)    = *(const float4*)(xe);
    *(float4*)(xa+4)  = *(const float4*)(xe+4);
    *(float4*)(xa+8)  = *(const float4*)(xe+512);
    *(float4*)(xa+12) = *(const float4*)(xe+516);
    float dv[8], sv[8];
    #pragma unroll
    for (int k2=0;k2<8;k2++){ dv[k2]=0.f; sv[k2]=0.f; }
    #pragma unroll
    for (int t=0;t<16;t++){
        float xv = xa[t];
        #pragma unroll
        for (int k2=0;k2<8;k2++){ dv[k2] += xv*wd[t][k2]; sv[k2] += xv*ws[t][k2]; }
    }
    float* dp = d + (size_t)idx*8;
    float* sp = s + (size_t)idx*8;
    *(float4*)(dp)   = make_float4(dv[0],dv[1],dv[2],dv[3]);
    *(float4*)(dp+4) = make_float4(dv[4],dv[5],dv[6],dv[7]);
    *(float4*)(sp)   = make_float4(sv[0],sv[1],sv[2],sv[3]);
    *(float4*)(sp+4) = make_float4(sv[4],sv[5],sv[6],sv[7]);
}

// ---------------- forward DFT ----------------
__global__ __launch_bounds__(256) void dft_kernel(
    const float* __restrict__ t0, const float* __restrict__ t1,
    const float* __restrict__ t2, const float* __restrict__ t3,
    float* __restrict__ S, int Lh, int m)
{
    __shared__ float2 tw2[512];
    __shared__ float pr[16][128], pi[16][128];
    const int tid = threadIdx.x;
    const int b = blockIdx.x, tensor = blockIdx.y, ck0 = blockIdx.z * 128;
    for (int r = tid; r < Lh; r += 256){
        float sv, cv;
        sincosf(6.283185307179586f * ((float)r / (float)Lh), &sv, &cv);
        tw2[r] = make_float2(cv, sv);
    }
    __syncthreads();
    const float* X = (tensor==0) ? t0 : (tensor==1) ? t1 : (tensor==2) ? t2 : t3;
    const int col  = tid & 127;
    const int half = tid >> 7;
    const int Lh2  = Lh >> 1;
    const float* p = X + ((size_t)b*Lh + (size_t)half*Lh2)*512 + ck0 + col;
    float ar[16], ai[16];
    #pragma unroll
    for (int f=0; f<16; f++){ ar[f]=0.f; ai[f]=0.f; }
    for (int li=0; li<Lh2; li++){
        const int l = half*Lh2 + li;
        float xv = p[(size_t)li*512];
        int r = 0;
        #pragma unroll
        for (int f=0; f<16; f++){
            float2 t = tw2[r];
            ar[f] += xv * t.x;
            ai[f] += xv * t.y;
            r += l; if (r >= Lh) r -= Lh;
        }
    }
    if (half){
        #pragma unroll
        for (int f=0; f<16; f++){ pr[f][col]=ar[f]; pi[f][col]=ai[f]; }
    }
    __syncthreads();
    if (!half){
        float* out = S + (((size_t)b*4 + tensor)*2*16)*512 + ck0 + col;
        for (int f=0; f<m; f++){
            out[(size_t)f*512]        =  ar[f] + pr[f][col];
            out[8192 + (size_t)f*512] = -(ai[f] + pi[f][col]);
        }
    }
}

// ---------------- mid: QK = ctanh(Sq^T Sk); O = QK Sk^T ----------------
__global__ __launch_bounds__(256) void mid_kernel(const float* __restrict__ S,
    float* __restrict__ O, int m)
{
    __shared__ float Sqr[64][16], Sqi[64][16], Skr[64][16], Ski[64][16];
    __shared__ float QKr[16][17], QKi[16][17];
    const int tid = threadIdx.x;
    const int b = blockIdx.x >> 3, h = blockIdx.x & 7;
    const int which = blockIdx.y;

    const float* base = S + (size_t)(b*4 + which*2)*2*16*512;
    for (int idx = tid; idx < 64*16; idx += 256){
        int e = idx >> 4, f = idx & 15;
        size_t o = (size_t)f*512 + e*8 + h;
        Sqr[e][f] = base[o];
        Sqi[e][f] = base[o + 8192];
        Skr[e][f] = base[o + 16384];
        Ski[e][f] = base[o + 24576];
    }
    __syncthreads();

    if (tid < m*m){
        int x = tid / m, y = tid - (tid/m)*m;
        float sr=0.f, sim=0.f;
        #pragma unroll 8
        for (int e=0;e<64;e++){
            float qr=Sqr[e][x], qi=Sqi[e][x];
            float kr=Skr[e][y], ki=Ski[e][y];
            sr  += qr*kr - qi*ki;
            sim += qr*ki + qi*kr;
        }
        float txx = tanhf(sr);
        float tyy = tanf(sim);
        float tx2=txx*txx, ty2=tyy*tyy;
        float den = 1.0f + tx2*ty2;
        QKr[x][y] = txx*(1.0f+ty2)/den;
        QKi[x][y] = tyy*(1.0f-tx2)/den;
    }
    __syncthreads();

    float* ob = O + (size_t)(b*2 + which)*2*16*512;
    for (int t = tid; t < 64*m; t += 256){
        int x = t % m, e = t / m;
        float orr=0.f, oii=0.f;
        for (int y=0;y<m;y++){
            float ar=QKr[x][y], ai2=QKi[x][y];
            float br=Skr[e][y], bi=Ski[e][y];
            orr += ar*br - ai2*bi;
            oii += ar*bi + ai2*br;
        }
        size_t o = (size_t)x*512 + e*8 + h;
        ob[o]        = orr;
        ob[o + 8192] = oii;
    }
}

// ---------------- inverse DFT + fused add ----------------
__global__ __launch_bounds__(256) void idft_kernel(const float* __restrict__ O,
    float* __restrict__ Us, float* __restrict__ Ud,
    int Lh, int m, float scale, int rows)
{
    __shared__ float twc[512], tws[512];
    __shared__ float Osm[2][2][16][128];
    const int tid = threadIdx.x;
    const int b = blockIdx.x, ck0 = blockIdx.y * 128;
    for (int r = tid; r < Lh; r += 256){
        float sv, cv;
        sincosf(6.283185307179586f * ((float)r / (float)Lh), &sv, &cv);
        twc[r]=cv; tws[r]=sv;
    }
    for (int idx = tid; idx < 2*2*16*128; idx += 256){
        int w    = idx >> 12;
        int rem  = idx & 4095;
        int reim = rem >> 11;
        int f    = (rem >> 7) & 15;
        int col  = rem & 127;
        Osm[w][reim][f][col] =
            O[(size_t)((b*2 + w)*2 + reim)*8192 + (size_t)f*512 + ck0 + col];
    }
    __syncthreads();
    const int l0 = blockIdx.z * rows;
    for (int t = tid; t < rows*128; t += 256){
        int lr = t >> 7, col = t & 127;
        int l = l0 + lr;
        float as = Osm[0][0][0][col];
        float ad = Osm[1][0][0][col];
        int r = 0;
        for (int f=1; f<m; f++){
            r += l; if (r >= Lh) r -= Lh;
            float c = twc[r], s = tws[r];
            as += 2.0f*(Osm[0][0][f][col]*c - Osm[0][1][f][col]*s);
            ad += 2.0f*(Osm[1][0][f][col]*c - Osm[1][1][f][col]*s);
        }
        size_t oi = ((size_t)b*Lh + l)*512 + ck0 + col;
        float usv = as * scale;
        Us[oi] = usv;
        Ud[oi] = ad * scale + usv;
    }
}

// ---------------- reconstruction ----------------
__global__ __launch_bounds__(256) void recon_kernel(const float* __restrict__ v,
    const float* __restrict__ Us, const float* __restrict__ Ud,
    const float* __restrict__ rce, const float* __restrict__ rco,
    float* __restrict__ outv, int Lv, int total)
{
    __shared__ float we[16][8], wo[16][8];
    int tid = threadIdx.x;
    if (tid < 128){ ((float*)we)[tid] = rce[tid]; ((float*)wo)[tid] = rco[tid]; }
    __syncthreads();
    int idx = blockIdx.x*256 + tid;
    if (idx >= total) return;
    int c = idx & 63;
    int l = (idx >> 6) % Lv;
    int b = idx / (Lv << 6);
    const float* vp = v  + (size_t)idx*8;
    const float* up = Us + (size_t)idx*8;
    const float* dp = Ud + (size_t)idx*8;
    float w[16];
    #pragma unroll
    for (int t=0;t<8;t++) w[t]   = vp[t] + up[t];
    #pragma unroll
    for (int t=0;t<8;t++) w[8+t] = dp[t];
    float ev[8], ov[8];
    #pragma unroll
    for (int k2=0;k2<8;k2++){ ev[k2]=0.f; ov[k2]=0.f; }
    #pragma unroll
    for (int t=0;t<16;t++){
        float xv = w[t];
        #pragma unroll
        for (int k2=0;k2<8;k2++){ ev[k2] += xv*we[t][k2]; ov[k2] += xv*wo[t][k2]; }
    }
    float* op = outv + (((size_t)b*(Lv<<1) + 2*l)*64 + c)*8;
    *(float4*)(op)     = make_float4(ev[0],ev[1],ev[2],ev[3]);
    *(float4*)(op+4)   = make_float4(ev[4],ev[5],ev[6],ev[7]);
    *(float4*)(op+512) = make_float4(ov[0],ov[1],ov[2],ov[3]);
    *(float4*)(op+516) = make_float4(ov[4],ov[5],ov[6],ov[7]);
}

// ---------------- orchestration ----------------
extern "C" void kernel_launch(void* const* d_in, const int* in_sizes, int n_in,
                              void* d_out, int out_size)
{
    (void)in_sizes; (void)n_in; (void)out_size;
    const float* q     = (const float*)d_in[0];
    const float* k     = (const float*)d_in[1];
    const float* Lq_w  = (const float*)d_in[3];
    const float* Lq_b  = (const float*)d_in[4];
    const float* Lk_w  = (const float*)d_in[5];
    const float* Lk_b  = (const float*)d_in[6];
    const float* out_w = (const float*)d_in[9];
    const float* out_b = (const float*)d_in[10];
    const float* ec_s  = (const float*)d_in[11];
    const float* ec_d  = (const float*)d_in[12];
    const float* rc_e  = (const float*)d_in[13];
    const float* rc_o  = (const float*)d_in[14];
    float* outp = (float*)d_out;

    float *bufA,*bufB,*kA,*kB,*dq,*dk,*us,*ud,*S,*O;
    __nv_bfloat16 *Wthi,*Wtlo,*W2hi,*W2lo,*W3hi,*W3lo;
    cudaGetSymbolAddress((void**)&bufA, g_bufA);
    cudaGetSymbolAddress((void**)&bufB, g_bufB);
    cudaGetSymbolAddress((void**)&kA,   g_kA);
    cudaGetSymbolAddress((void**)&kB,   g_kB);
    cudaGetSymbolAddress((void**)&dq,   g_dq);
    cudaGetSymbolAddress((void**)&dk,   g_dk);
    cudaGetSymbolAddress((void**)&us,   g_Us);
    cudaGetSymbolAddress((void**)&ud,   g_Ud);
    cudaGetSymbolAddress((void**)&S,    g_S);
    cudaGetSymbolAddress((void**)&O,    g_O);
    cudaGetSymbolAddress((void**)&Wthi, g_Wthi);
    cudaGetSymbolAddress((void**)&Wtlo, g_Wtlo);
    cudaGetSymbolAddress((void**)&W2hi, g_W2hi);
    cudaGetSymbolAddress((void**)&W2lo, g_W2lo);
    cudaGetSymbolAddress((void**)&W3hi, g_W3hi);
    cudaGetSymbolAddress((void**)&W3lo, g_W3lo);

    cudaFuncSetAttribute(gemm_mma,  cudaFuncAttributeMaxDynamicSharedMemorySize, GEMM_SMEM);
    cudaFuncSetAttribute(gemm_mma2, cudaFuncAttributeMaxDynamicSharedMemorySize, GEMM_SMEM);

    size_t offs[10]; size_t off=0;
    { int L = 1024;
      for (int i=0;i<10;i++){ int Lh = L >> 1; offs[i] = off; off += (size_t)16*Lh*512; L = Lh; } }

    convW3_kernel<<<dim3(16,16,3),256>>>(Lq_w, Lk_w, out_w,
                                         Wthi, Wtlo, W2hi, W2lo, W3hi, W3lo);
    zero2_kernel<<<32,256>>>(us+offs[9], ud+offs[9], 16*1*512);
    gemm_mma2<<<dim3(4,128,2),256,GEMM_SMEM>>>(q, k, Wthi, Wtlo, W2hi, W2lo,
                                               Lq_b, Lk_b, bufA, kA);

    // levels 0..8: proven per-level pipeline (wavelet_qk + dft + mid + idft)
    float *qc=bufA,*qn=bufB,*kc=kA,*kn=kB;
    int L = 1024;
    for (int i=0;i<9;i++){
        int Lh = L >> 1;
        int m  = (Lh>>1) < 16 ? (Lh>>1) : 16;
        int total = 16*Lh*64;
        int blocks = (total + 255)/256;
        wavelet_qk<<<dim3(blocks,1,2),256>>>(qc, dq, qn, kc, dk, kn, ec_d, ec_s, Lh, total);
        dft_kernel<<<dim3(16,4,4),256>>>(dq, dk, qn, kn, S, Lh, m);
        mid_kernel<<<dim3(128,2),256>>>(S, O, m);
        float inv_scale = 1.0f/(4096.0f*(float)Lh);
        int lsplit = (Lh >= 64) ? (Lh/64) : 1;
        int rows   = Lh / lsplit;
        idft_kernel<<<dim3(16,4,lsplit),256>>>(O, us+offs[i], ud+offs[i], Lh, m, inv_scale, rows);
        float* t; t=qc; qc=qn; qn=t;  t=kc; kc=kn; kn=t;
        L = Lh;
    }

    // v = FCA at L=1 = zeros; reconstruct upward (full 10-step proven chain)
    float *vc=qc, *vn=qn;
    zero_kernel<<<32,256>>>(vc, 16*1*512);
    int Lv = 1;
    for (int i=9;i>=0;i--){
        int total = 16*Lv*64;
        recon_kernel<<<(total+255)/256,256>>>(vc, us+offs[i], ud+offs[i],
                                              rc_e, rc_o, vn, Lv, total);
        float* t=vc; vc=vn; vn=t;
        Lv <<= 1;
    }

    gemm_mma<<<dim3(4,128),256,GEMM_SMEM>>>(vc, W3hi, W3lo, out_b, outp);
}